// round 1
// baseline (speedup 1.0000x reference)
#include <cuda_runtime.h>
#include <math.h>

// Problem constants
#define NB   16
#define NSEQ 1024
#define CH   64
#define KKD  8
#define CK   512          // C*K
#define MROWS (NB*NSEQ)   // 16384

// -------- scratch (device globals; no allocation allowed) --------
__device__ float g_bufA[NB*NSEQ*CK];
__device__ float g_bufB[NB*NSEQ*CK];
__device__ float g_kA[NB*NSEQ*CK];
__device__ float g_kB[NB*NSEQ*CK];
__device__ float g_dq[NB*512*CK];
__device__ float g_dk[NB*512*CK];
__device__ float g_Us[NB*1023*CK];
__device__ float g_Ud[NB*1023*CK];

// ---------------- SGEMM: C[M,512] = A[M,512] @ W[512,512] + bias ----------------
__global__ __launch_bounds__(256) void sgemm512(const float* __restrict__ A,
    const float* __restrict__ W, const float* __restrict__ bias,
    float* __restrict__ C)
{
    __shared__ float As[8][128];
    __shared__ float Bs[8][128];
    const int tid = threadIdx.x;
    const int bx = blockIdx.x, by = blockIdx.y;
    const int arow = tid >> 1, acol = (tid & 1) << 2;
    const int brow = tid >> 5, bcol = (tid & 31) << 2;
    const float* Ap = A + ((size_t)by*128 + arow)*512 + acol;
    const float* Wp = W + (size_t)brow*512 + bx*128 + bcol;
    const int ty = tid >> 4, tx = tid & 15;
    float acc[8][8];
    #pragma unroll
    for (int i=0;i<8;i++)
        #pragma unroll
        for (int j=0;j<8;j++) acc[i][j]=0.f;
    for (int kk=0; kk<512; kk+=8){
        float4 av = *(const float4*)(Ap + kk);
        float4 bv = *(const float4*)(Wp + (size_t)kk*512);
        As[acol+0][arow]=av.x; As[acol+1][arow]=av.y;
        As[acol+2][arow]=av.z; As[acol+3][arow]=av.w;
        *(float4*)(&Bs[brow][bcol]) = bv;
        __syncthreads();
        #pragma unroll
        for (int k=0;k<8;k++){
            float a[8], bb[8];
            *(float4*)(a)    = *(const float4*)(&As[k][ty*8]);
            *(float4*)(a+4)  = *(const float4*)(&As[k][ty*8+4]);
            *(float4*)(bb)   = *(const float4*)(&Bs[k][tx*8]);
            *(float4*)(bb+4) = *(const float4*)(&Bs[k][tx*8+4]);
            #pragma unroll
            for (int i=0;i<8;i++)
                #pragma unroll
                for (int j=0;j<8;j++) acc[i][j] += a[i]*bb[j];
        }
        __syncthreads();
    }
    #pragma unroll
    for (int i=0;i<8;i++){
        float* cp = C + ((size_t)by*128 + ty*8 + i)*512 + bx*128 + tx*8;
        #pragma unroll
        for (int j=0;j<8;j++) cp[j] = acc[i][j] + bias[bx*128 + tx*8 + j];
    }
}

// ---------------- wavelet: x(b,2Lh,C,K) -> d,s (b,Lh,C,K) ----------------
__global__ __launch_bounds__(256) void wavelet_kernel(const float* __restrict__ x,
    float* __restrict__ d, float* __restrict__ s,
    const float* __restrict__ ecd, const float* __restrict__ ecs,
    int Lh, int total)
{
    __shared__ float wd[16][8], ws[16][8];
    int tid = threadIdx.x;
    if (tid < 128){ ((float*)wd)[tid] = ecd[tid]; ((float*)ws)[tid] = ecs[tid]; }
    __syncthreads();
    int idx = blockIdx.x*256 + tid;
    if (idx >= total) return;
    int c = idx & 63;
    int j = (idx >> 6) % Lh;
    int b = idx / (Lh << 6);
    const float* xe = x + (((size_t)b*(Lh<<1) + 2*j)*64 + c)*8;
    float xa[16];
    *(float4*)(xa)    = *(const float4*)(xe);
    *(float4*)(xa+4)  = *(const float4*)(xe+4);
    *(float4*)(xa+8)  = *(const float4*)(xe+512);
    *(float4*)(xa+12) = *(const float4*)(xe+516);
    float dv[8], sv[8];
    #pragma unroll
    for (int k=0;k<8;k++){ dv[k]=0.f; sv[k]=0.f; }
    #pragma unroll
    for (int t=0;t<16;t++){
        float xv = xa[t];
        #pragma unroll
        for (int k=0;k<8;k++){ dv[k] += xv*wd[t][k]; sv[k] += xv*ws[t][k]; }
    }
    float* dp = d + (size_t)idx*8;
    float* sp = s + (size_t)idx*8;
    *(float4*)(dp)   = make_float4(dv[0],dv[1],dv[2],dv[3]);
    *(float4*)(dp+4) = make_float4(dv[4],dv[5],dv[6],dv[7]);
    *(float4*)(sp)   = make_float4(sv[0],sv[1],sv[2],sv[3]);
    *(float4*)(sp+4) = make_float4(sv[4],sv[5],sv[6],sv[7]);
}

// ---------------- Fourier cross attention (one block per (b,h)) ----------------
// X,Y: (b,Lh,64,8). out = irfft( pad_m( tanh(Xq^T Xk) @ Xk^T ) / 4096, n=Lh )
__global__ __launch_bounds__(256) void fca_kernel(
    const float* __restrict__ X, const float* __restrict__ Y,
    float* __restrict__ out, const float* __restrict__ addend,
    int Lh, int m, float inv_scale)
{
    __shared__ float twc[512], tws[512];
    __shared__ float Sr[2][64][17], Si[2][64][17];   // 0 = q spectra, 1 = k spectra
    __shared__ float QKr[16][17], QKi[16][17];
    __shared__ float Or_[64][17], Oi_[64][17];
    const int tid = threadIdx.x;
    const int b = blockIdx.x >> 3, h = blockIdx.x & 7;

    // twiddle table: tw[r] = (cos, sin)(2*pi*r/Lh); index = (f*l) mod Lh
    for (int r = tid; r < Lh; r += 256){
        float sv, cv;
        sincosf(6.283185307179586f * ((float)r / (float)Lh), &sv, &cv);
        twc[r]=cv; tws[r]=sv;
    }
    __syncthreads();

    // Phase 1: forward DFT, first m modes. thread -> (tensor, e, half-of-modes)
    {
        int fhalf  = tid & 1;
        int e      = (tid >> 1) & 63;
        int tensor = tid >> 7;
        int f0     = fhalf << 3;
        int fcnt   = m - f0; if (fcnt > 8) fcnt = 8;
        if (fcnt > 0){
            const float* src = tensor ? Y : X;
            const float* p = src + (size_t)b*Lh*512 + e*8 + h;
            float ar[8], ai[8];
            #pragma unroll
            for (int i=0;i<8;i++){ ar[i]=0.f; ai[i]=0.f; }
            int r0 = 0;                       // (f0*l) mod Lh
            for (int l=0;l<Lh;l++){
                float xv = p[(size_t)l*512];
                int r = r0;
                for (int fi=0; fi<fcnt; fi++){
                    ar[fi] += xv*twc[r];
                    ai[fi] -= xv*tws[r];
                    r += l; if (r >= Lh) r -= Lh;
                }
                r0 += f0; if (r0 >= Lh) r0 -= Lh;
            }
            for (int fi=0; fi<fcnt; fi++){
                Sr[tensor][e][f0+fi] = ar[fi];
                Si[tensor][e][f0+fi] = ai[fi];
            }
        }
    }
    __syncthreads();

    // Phase 2: QK[x,y] = tanh( sum_e Xq[e,x]*Xk[e,y] )   (complex tanh)
    for (int t = tid; t < m*m; t += 256){
        int x = t / m, y = t - x*m;
        float sr=0.f, sim=0.f;
        #pragma unroll 8
        for (int e=0;e<64;e++){
            float qr=Sr[0][e][x], qi=Si[0][e][x];
            float kr=Sr[1][e][y], ki=Si[1][e][y];
            sr  += qr*kr - qi*ki;
            sim += qr*ki + qi*kr;
        }
        float txx = tanhf(sr);
        float tyy = tanf(sim);
        float tx2=txx*txx, ty2=tyy*tyy;
        float den = 1.0f + tx2*ty2;
        QKr[x][y] = txx*(1.0f+ty2)/den;
        QKi[x][y] = tyy*(1.0f-tx2)/den;
    }
    __syncthreads();

    // Phase 3: O[e,x] = sum_y QK[x,y]*Xk[e,y]
    for (int t = tid; t < 64*m; t += 256){
        int x = t % m, e = t / m;
        float orr=0.f, oii=0.f;
        for (int y=0;y<m;y++){
            float ar=QKr[x][y], ai2=QKi[x][y];
            float br=Sr[1][e][y], bi=Si[1][e][y];
            orr += ar*br - ai2*bi;
            oii += ar*bi + ai2*br;
        }
        Or_[e][x]=orr; Oi_[e][x]=oii;
    }
    __syncthreads();

    // Phase 4: inverse rFFT (only m modes nonzero), scale, optional addend
    for (int t = tid; t < Lh*64; t += 256){
        int l = t >> 6, e = t & 63;
        float acc = 0.f;
        if (m > 0){
            acc = Or_[e][0];
            int r = 0;                        // (f*l) mod Lh
            for (int f=1; f<m; f++){
                r += l; if (r >= Lh) r -= Lh;
                acc += 2.0f*(Or_[e][f]*twc[r] - Oi_[e][f]*tws[r]);
            }
        }
        size_t oidx = (((size_t)b*Lh + l)*64 + e)*8 + h;
        float val = acc * inv_scale;
        if (addend) val += addend[oidx];
        out[oidx] = val;
    }
}

// ---------------- reconstruction: (v+Us | Ud) @ rc_e / rc_o, interleave even/odd ----------------
__global__ __launch_bounds__(256) void recon_kernel(const float* __restrict__ v,
    const float* __restrict__ Us, const float* __restrict__ Ud,
    const float* __restrict__ rce, const float* __restrict__ rco,
    float* __restrict__ outv, int Lv, int total)
{
    __shared__ float we[16][8], wo[16][8];
    int tid = threadIdx.x;
    if (tid < 128){ ((float*)we)[tid] = rce[tid]; ((float*)wo)[tid] = rco[tid]; }
    __syncthreads();
    int idx = blockIdx.x*256 + tid;
    if (idx >= total) return;
    int c = idx & 63;
    int l = (idx >> 6) % Lv;
    int b = idx / (Lv << 6);
    const float* vp = v  + (size_t)idx*8;
    const float* up = Us + (size_t)idx*8;
    const float* dp = Ud + (size_t)idx*8;
    float w[16];
    #pragma unroll
    for (int t=0;t<8;t++) w[t]   = vp[t] + up[t];
    #pragma unroll
    for (int t=0;t<8;t++) w[8+t] = dp[t];
    float ev[8], ov[8];
    #pragma unroll
    for (int k=0;k<8;k++){ ev[k]=0.f; ov[k]=0.f; }
    #pragma unroll
    for (int t=0;t<16;t++){
        float xv = w[t];
        #pragma unroll
        for (int k=0;k<8;k++){ ev[k] += xv*we[t][k]; ov[k] += xv*wo[t][k]; }
    }
    float* op = outv + (((size_t)b*(Lv<<1) + 2*l)*64 + c)*8;
    *(float4*)(op)     = make_float4(ev[0],ev[1],ev[2],ev[3]);
    *(float4*)(op+4)   = make_float4(ev[4],ev[5],ev[6],ev[7]);
    *(float4*)(op+512) = make_float4(ov[0],ov[1],ov[2],ov[3]);
    *(float4*)(op+516) = make_float4(ov[4],ov[5],ov[6],ov[7]);
}

__global__ void zero_kernel(float* p, int n){
    int i = blockIdx.x*blockDim.x + threadIdx.x;
    if (i < n) p[i] = 0.f;
}

// ---------------- orchestration ----------------
extern "C" void kernel_launch(void* const* d_in, const int* in_sizes, int n_in,
                              void* d_out, int out_size)
{
    (void)in_sizes; (void)n_in; (void)out_size;
    const float* q     = (const float*)d_in[0];
    const float* k     = (const float*)d_in[1];
    // d_in[2] (v), d_in[7] (Lv_w), d_in[8] (Lv_b) are provably unused by the math
    const float* Lq_w  = (const float*)d_in[3];
    const float* Lq_b  = (const float*)d_in[4];
    const float* Lk_w  = (const float*)d_in[5];
    const float* Lk_b  = (const float*)d_in[6];
    const float* out_w = (const float*)d_in[9];
    const float* out_b = (const float*)d_in[10];
    const float* ec_s  = (const float*)d_in[11];
    const float* ec_d  = (const float*)d_in[12];
    const float* rc_e  = (const float*)d_in[13];
    const float* rc_o  = (const float*)d_in[14];
    float* outp = (float*)d_out;

    float *bufA,*bufB,*kA,*kB,*dq,*dk,*us,*ud;
    cudaGetSymbolAddress((void**)&bufA, g_bufA);
    cudaGetSymbolAddress((void**)&bufB, g_bufB);
    cudaGetSymbolAddress((void**)&kA,   g_kA);
    cudaGetSymbolAddress((void**)&kB,   g_kB);
    cudaGetSymbolAddress((void**)&dq,   g_dq);
    cudaGetSymbolAddress((void**)&dk,   g_dk);
    cudaGetSymbolAddress((void**)&us,   g_Us);
    cudaGetSymbolAddress((void**)&ud,   g_Ud);

    dim3 ggrid(4,128);
    sgemm512<<<ggrid,256>>>(q, Lq_w, Lq_b, bufA);
    sgemm512<<<ggrid,256>>>(k, Lk_w, Lk_b, kA);

    float *qc=bufA,*qn=bufB,*kc=kA,*kn=kB;
    size_t offs[10]; size_t off=0;
    int L = 1024;
    for (int i=0;i<10;i++){
        int Lh = L >> 1;
        int m  = (Lh>>1) < 16 ? (Lh>>1) : 16;
        int total = 16*Lh*64;
        int blocks = (total + 255)/256;
        wavelet_kernel<<<blocks,256>>>(qc, dq, qn, ec_d, ec_s, Lh, total);
        wavelet_kernel<<<blocks,256>>>(kc, dk, kn, ec_d, ec_s, Lh, total);
        float inv_scale = 1.0f/(4096.0f*(float)Lh);
        // Us[i] = FCA(dq,dk);  Ud[i] = FCA(q,k) + Us[i]
        fca_kernel<<<128,256>>>(dq, dk, us+off, (const float*)0, Lh, m, inv_scale);
        fca_kernel<<<128,256>>>(qn, kn, ud+off, us+off,          Lh, m, inv_scale);
        offs[i] = off; off += (size_t)16*Lh*512;
        float* t; t=qc; qc=qn; qn=t;  t=kc; kc=kn; kn=t;
        L = Lh;
    }

    // v = FCA at L=1 = zeros; reconstruct upward
    float *vc=bufA, *vn=bufB;
    zero_kernel<<<32,256>>>(vc, 16*1*512);
    int Lv = 1;
    for (int i=9;i>=0;i--){
        int total = 16*Lv*64;
        recon_kernel<<<(total+255)/256,256>>>(vc, us+offs[i], ud+offs[i],
                                              rc_e, rc_o, vn, Lv, total);
        float* t=vc; vc=vn; vn=t;
        Lv <<= 1;
    }
    sgemm512<<<ggrid,256>>>(vc, out_w, out_b, outp);
}

// round 4
// speedup vs baseline: 1.3500x; 1.3500x over previous
#include <cuda_runtime.h>
#include <math.h>

// Problem constants
#define NB   16
#define NSEQ 1024
#define CK   512          // C*K

// -------- scratch (device globals; no allocation allowed) --------
__device__ float g_bufA[NB*NSEQ*CK];
__device__ float g_bufB[NB*NSEQ*CK];
__device__ float g_kA[NB*NSEQ*CK];
__device__ float g_kB[NB*NSEQ*CK];
__device__ float g_dq[NB*512*CK];
__device__ float g_dk[NB*512*CK];
__device__ float g_Us[NB*1023*CK];
__device__ float g_Ud[NB*1023*CK];
__device__ float g_S[NB*4*2*16*CK];   // spectra: (b, tensor{dq,dk,qn,kn}, re/im, mode, ck)
__device__ float g_O[NB*2*2*16*CK];   // post-attn spectra: (b, which{s,d}, re/im, mode, ck)

// ---------------- SGEMM: C[M,512] = A[M,512] @ W[512,512] + bias ----------------
__global__ __launch_bounds__(256) void sgemm512(const float* __restrict__ A,
    const float* __restrict__ W, const float* __restrict__ bias,
    float* __restrict__ C)
{
    __shared__ float As[8][128];
    __shared__ float Bs[8][128];
    const int tid = threadIdx.x;
    const int bx = blockIdx.x, by = blockIdx.y;
    const int arow = tid >> 1, acol = (tid & 1) << 2;
    const int brow = tid >> 5, bcol = (tid & 31) << 2;
    const float* Ap = A + ((size_t)by*128 + arow)*512 + acol;
    const float* Wp = W + (size_t)brow*512 + bx*128 + bcol;
    const int ty = tid >> 4, tx = tid & 15;
    float acc[8][8];
    #pragma unroll
    for (int i=0;i<8;i++)
        #pragma unroll
        for (int j=0;j<8;j++) acc[i][j]=0.f;
    for (int kk=0; kk<512; kk+=8){
        float4 av = *(const float4*)(Ap + kk);
        float4 bv = *(const float4*)(Wp + (size_t)kk*512);
        As[acol+0][arow]=av.x; As[acol+1][arow]=av.y;
        As[acol+2][arow]=av.z; As[acol+3][arow]=av.w;
        *(float4*)(&Bs[brow][bcol]) = bv;
        __syncthreads();
        #pragma unroll
        for (int k=0;k<8;k++){
            float a[8], bb[8];
            *(float4*)(a)    = *(const float4*)(&As[k][ty*8]);
            *(float4*)(a+4)  = *(const float4*)(&As[k][ty*8+4]);
            *(float4*)(bb)   = *(const float4*)(&Bs[k][tx*8]);
            *(float4*)(bb+4) = *(const float4*)(&Bs[k][tx*8+4]);
            #pragma unroll
            for (int i=0;i<8;i++)
                #pragma unroll
                for (int j=0;j<8;j++) acc[i][j] += a[i]*bb[j];
        }
        __syncthreads();
    }
    #pragma unroll
    for (int i=0;i<8;i++){
        float* cp = C + ((size_t)by*128 + ty*8 + i)*512 + bx*128 + tx*8;
        #pragma unroll
        for (int j=0;j<8;j++) cp[j] = acc[i][j] + bias[bx*128 + tx*8 + j];
    }
}

// ---------------- wavelet: x(b,2Lh,C,K) -> d,s (b,Lh,C,K) ----------------
__global__ __launch_bounds__(256) void wavelet_kernel(const float* __restrict__ x,
    float* __restrict__ d, float* __restrict__ s,
    const float* __restrict__ ecd, const float* __restrict__ ecs,
    int Lh, int total)
{
    __shared__ float wd[16][8], ws[16][8];
    int tid = threadIdx.x;
    if (tid < 128){ ((float*)wd)[tid] = ecd[tid]; ((float*)ws)[tid] = ecs[tid]; }
    __syncthreads();
    int idx = blockIdx.x*256 + tid;
    if (idx >= total) return;
    int c = idx & 63;
    int j = (idx >> 6) % Lh;
    int b = idx / (Lh << 6);
    const float* xe = x + (((size_t)b*(Lh<<1) + 2*j)*64 + c)*8;
    float xa[16];
    *(float4*)(xa)    = *(const float4*)(xe);
    *(float4*)(xa+4)  = *(const float4*)(xe+4);
    *(float4*)(xa+8)  = *(const float4*)(xe+512);
    *(float4*)(xa+12) = *(const float4*)(xe+516);
    float dv[8], sv[8];
    #pragma unroll
    for (int k=0;k<8;k++){ dv[k]=0.f; sv[k]=0.f; }
    #pragma unroll
    for (int t=0;t<16;t++){
        float xv = xa[t];
        #pragma unroll
        for (int k=0;k<8;k++){ dv[k] += xv*wd[t][k]; sv[k] += xv*ws[t][k]; }
    }
    float* dp = d + (size_t)idx*8;
    float* sp = s + (size_t)idx*8;
    *(float4*)(dp)   = make_float4(dv[0],dv[1],dv[2],dv[3]);
    *(float4*)(dp+4) = make_float4(dv[4],dv[5],dv[6],dv[7]);
    *(float4*)(sp)   = make_float4(sv[0],sv[1],sv[2],sv[3]);
    *(float4*)(sp+4) = make_float4(sv[4],sv[5],sv[6],sv[7]);
}

// ---------------- forward DFT: S[b,tensor,re/im,f,ck] = sum_l X[b,l,ck] * e^{-i 2pi f l / Lh} ----
// grid: (16, 4 tensors, 4 ck-tiles of 128). threads: 256 = 128 cols x 2 halves (cos/sin).
__global__ __launch_bounds__(256) void dft_kernel(
    const float* __restrict__ t0, const float* __restrict__ t1,
    const float* __restrict__ t2, const float* __restrict__ t3,
    float* __restrict__ S, int Lh, int m)
{
    __shared__ float twc[512], tws[512];
    const int tid = threadIdx.x;
    const int b = blockIdx.x, tensor = blockIdx.y, ck0 = blockIdx.z * 128;
    for (int r = tid; r < Lh; r += 256){
        float sv, cv;
        sincosf(6.283185307179586f * ((float)r / (float)Lh), &sv, &cv);
        twc[r]=cv; tws[r]=sv;
    }
    __syncthreads();
    const float* X = (tensor==0) ? t0 : (tensor==1) ? t1 : (tensor==2) ? t2 : t3;
    const int col = tid & 127;
    const int half = tid >> 7;          // 0 = cos (real), 1 = sin (-imag)
    const float* tw = half ? tws : twc;
    const float* p = X + (size_t)b*Lh*512 + ck0 + col;
    float acc[16];
    #pragma unroll
    for (int f=0; f<16; f++) acc[f]=0.f;
    #pragma unroll 2
    for (int l=0; l<Lh; l++){
        float xv = p[(size_t)l*512];
        int r = 0;
        #pragma unroll
        for (int f=0; f<16; f++){
            acc[f] += xv * tw[r];
            r += l; if (r >= Lh) r -= Lh;
        }
    }
    float sgn = half ? -1.0f : 1.0f;    // imag = -sum x*sin
    float* out = S + ((((size_t)b*4 + tensor)*2 + half)*16)*512 + ck0 + col;
    for (int f=0; f<m; f++)
        out[(size_t)f*512] = sgn * acc[f];
}

// ---------------- mid: QK = ctanh(Sq^T Sk); O = QK Sk^T. grid (128 bh, 2 which) ----------------
__global__ __launch_bounds__(256) void mid_kernel(const float* __restrict__ S,
    float* __restrict__ O, int m)
{
    __shared__ float Sqr[64][16], Sqi[64][16], Skr[64][16], Ski[64][16];
    __shared__ float QKr[16][17], QKi[16][17];
    const int tid = threadIdx.x;
    const int b = blockIdx.x >> 3, h = blockIdx.x & 7;
    const int which = blockIdx.y;   // 0: (dq,dk) -> Us-path; 1: (qn,kn) -> d-path

    const float* base = S + (size_t)(b*4 + which*2)*2*16*512;
    for (int idx = tid; idx < 64*16; idx += 256){
        int e = idx >> 4, f = idx & 15;
        size_t o = (size_t)f*512 + e*8 + h;
        Sqr[e][f] = base[o];
        Sqi[e][f] = base[o + 8192];
        Skr[e][f] = base[o + 16384];
        Ski[e][f] = base[o + 24576];
    }
    __syncthreads();

    if (tid < m*m){
        int x = tid / m, y = tid - x*m;
        float sr=0.f, sim=0.f;
        #pragma unroll 8
        for (int e=0;e<64;e++){
            float qr=Sqr[e][x], qi=Sqi[e][x];
            float kr=Skr[e][y], ki=Ski[e][y];
            sr  += qr*kr - qi*ki;
            sim += qr*ki + qi*kr;
        }
        float txx = tanhf(sr);
        float tyy = tanf(sim);
        float tx2=txx*txx, ty2=tyy*tyy;
        float den = 1.0f + tx2*ty2;
        QKr[x][y] = txx*(1.0f+ty2)/den;
        QKi[x][y] = tyy*(1.0f-tx2)/den;
    }
    __syncthreads();

    float* ob = O + (size_t)(b*2 + which)*2*16*512;
    for (int t = tid; t < 64*m; t += 256){
        int x = t % m, e = t / m;
        float orr=0.f, oii=0.f;
        for (int y=0;y<m;y++){
            float ar=QKr[x][y], ai2=QKi[x][y];
            float br=Skr[e][y], bi=Ski[e][y];
            orr += ar*br - ai2*bi;
            oii += ar*bi + ai2*br;
        }
        size_t o = (size_t)x*512 + e*8 + h;
        ob[o]        = orr;
        ob[o + 8192] = oii;
    }
}

// ---------------- inverse DFT + scale + fused add: Us = idft(O_s)*s; Ud = idft(O_d)*s + Us ----
// grid: (16 b, 4 ck-tiles, lsplit). threads 256.
__global__ __launch_bounds__(256) void idft_kernel(const float* __restrict__ O,
    float* __restrict__ Us, float* __restrict__ Ud,
    int Lh, int m, float scale, int rows)
{
    __shared__ float twc[512], tws[512];
    __shared__ float Osm[2][2][16][128];
    const int tid = threadIdx.x;
    const int b = blockIdx.x, ck0 = blockIdx.y * 128;
    for (int r = tid; r < Lh; r += 256){
        float sv, cv;
        sincosf(6.283185307179586f * ((float)r / (float)Lh), &sv, &cv);
        twc[r]=cv; tws[r]=sv;
    }
    for (int idx = tid; idx < 2*2*16*128; idx += 256){
        int w    = idx >> 12;
        int rem  = idx & 4095;
        int reim = rem >> 11;
        int f    = (rem >> 7) & 15;
        int col  = rem & 127;
        Osm[w][reim][f][col] =
            O[(size_t)((b*2 + w)*2 + reim)*8192 + (size_t)f*512 + ck0 + col];
    }
    __syncthreads();
    const int l0 = blockIdx.z * rows;
    for (int t = tid; t < rows*128; t += 256){
        int lr = t >> 7, col = t & 127;
        int l = l0 + lr;
        float as = Osm[0][0][0][col];
        float ad = Osm[1][0][0][col];
        int r = 0;
        for (int f=1; f<m; f++){
            r += l; if (r >= Lh) r -= Lh;
            float c = twc[r], s = tws[r];
            as += 2.0f*(Osm[0][0][f][col]*c - Osm[0][1][f][col]*s);
            ad += 2.0f*(Osm[1][0][f][col]*c - Osm[1][1][f][col]*s);
        }
        size_t oi = ((size_t)b*Lh + l)*512 + ck0 + col;
        float usv = as * scale;
        Us[oi] = usv;
        Ud[oi] = ad * scale + usv;
    }
}

// ---------------- reconstruction: (v+Us | Ud) @ rc_e / rc_o, interleave even/odd ----------------
__global__ __launch_bounds__(256) void recon_kernel(const float* __restrict__ v,
    const float* __restrict__ Us, const float* __restrict__ Ud,
    const float* __restrict__ rce, const float* __restrict__ rco,
    float* __restrict__ outv, int Lv, int total)
{
    __shared__ float we[16][8], wo[16][8];
    int tid = threadIdx.x;
    if (tid < 128){ ((float*)we)[tid] = rce[tid]; ((float*)wo)[tid] = rco[tid]; }
    __syncthreads();
    int idx = blockIdx.x*256 + tid;
    if (idx >= total) return;
    int c = idx & 63;
    int l = (idx >> 6) % Lv;
    int b = idx / (Lv << 6);
    const float* vp = v  + (size_t)idx*8;
    const float* up = Us + (size_t)idx*8;
    const float* dp = Ud + (size_t)idx*8;
    float w[16];
    #pragma unroll
    for (int t=0;t<8;t++) w[t]   = vp[t] + up[t];
    #pragma unroll
    for (int t=0;t<8;t++) w[8+t] = dp[t];
    float ev[8], ov[8];
    #pragma unroll
    for (int k=0;k<8;k++){ ev[k]=0.f; ov[k]=0.f; }
    #pragma unroll
    for (int t=0;t<16;t++){
        float xv = w[t];
        #pragma unroll
        for (int k=0;k<8;k++){ ev[k] += xv*we[t][k]; ov[k] += xv*wo[t][k]; }
    }
    float* op = outv + (((size_t)b*(Lv<<1) + 2*l)*64 + c)*8;
    *(float4*)(op)     = make_float4(ev[0],ev[1],ev[2],ev[3]);
    *(float4*)(op+4)   = make_float4(ev[4],ev[5],ev[6],ev[7]);
    *(float4*)(op+512) = make_float4(ov[0],ov[1],ov[2],ov[3]);
    *(float4*)(op+516) = make_float4(ov[4],ov[5],ov[6],ov[7]);
}

__global__ void zero_kernel(float* p, int n){
    int i = blockIdx.x*blockDim.x + threadIdx.x;
    if (i < n) p[i] = 0.f;
}

// ---------------- orchestration ----------------
extern "C" void kernel_launch(void* const* d_in, const int* in_sizes, int n_in,
                              void* d_out, int out_size)
{
    (void)in_sizes; (void)n_in; (void)out_size;
    const float* q     = (const float*)d_in[0];
    const float* k     = (const float*)d_in[1];
    // d_in[2] (v), d_in[7] (Lv_w), d_in[8] (Lv_b) provably unused by the math
    const float* Lq_w  = (const float*)d_in[3];
    const float* Lq_b  = (const float*)d_in[4];
    const float* Lk_w  = (const float*)d_in[5];
    const float* Lk_b  = (const float*)d_in[6];
    const float* out_w = (const float*)d_in[9];
    const float* out_b = (const float*)d_in[10];
    const float* ec_s  = (const float*)d_in[11];
    const float* ec_d  = (const float*)d_in[12];
    const float* rc_e  = (const float*)d_in[13];
    const float* rc_o  = (const float*)d_in[14];
    float* outp = (float*)d_out;

    float *bufA,*bufB,*kA,*kB,*dq,*dk,*us,*ud,*S,*O;
    cudaGetSymbolAddress((void**)&bufA, g_bufA);
    cudaGetSymbolAddress((void**)&bufB, g_bufB);
    cudaGetSymbolAddress((void**)&kA,   g_kA);
    cudaGetSymbolAddress((void**)&kB,   g_kB);
    cudaGetSymbolAddress((void**)&dq,   g_dq);
    cudaGetSymbolAddress((void**)&dk,   g_dk);
    cudaGetSymbolAddress((void**)&us,   g_Us);
    cudaGetSymbolAddress((void**)&ud,   g_Ud);
    cudaGetSymbolAddress((void**)&S,    g_S);
    cudaGetSymbolAddress((void**)&O,    g_O);

    dim3 ggrid(4,128);
    sgemm512<<<ggrid,256>>>(q, Lq_w, Lq_b, bufA);
    sgemm512<<<ggrid,256>>>(k, Lk_w, Lk_b, kA);

    float *qc=bufA,*qn=bufB,*kc=kA,*kn=kB;
    size_t offs[10]; size_t off=0;
    int L = 1024;
    for (int i=0;i<10;i++){
        int Lh = L >> 1;
        int m  = (Lh>>1) < 16 ? (Lh>>1) : 16;
        if (m > 0){
            int total = 16*Lh*64;
            int blocks = (total + 255)/256;
            wavelet_kernel<<<blocks,256>>>(qc, dq, qn, ec_d, ec_s, Lh, total);
            wavelet_kernel<<<blocks,256>>>(kc, dk, kn, ec_d, ec_s, Lh, total);
            dft_kernel<<<dim3(16,4,4),256>>>(dq, dk, qn, kn, S, Lh, m);
            mid_kernel<<<dim3(128,2),256>>>(S, O, m);
            float inv_scale = 1.0f/(4096.0f*(float)Lh);
            int lsplit = (Lh >= 64) ? (Lh/64) : 1;
            int rows   = Lh / lsplit;
            idft_kernel<<<dim3(16,4,lsplit),256>>>(O, us+off, ud+off, Lh, m, inv_scale, rows);
        } else {
            // Lh==1: m=0 -> FCA outputs are zero; wavelets feeding them are dead.
            zero_kernel<<<32,256>>>(us+off, 16*1*512);
            zero_kernel<<<32,256>>>(ud+off, 16*1*512);
        }
        offs[i] = off; off += (size_t)16*Lh*512;
        float* t; t=qc; qc=qn; qn=t;  t=kc; kc=kn; kn=t;
        L = Lh;
    }

    // v = FCA at L=1 = zeros; reconstruct upward
    float *vc=bufA, *vn=bufB;
    zero_kernel<<<32,256>>>(vc, 16*1*512);
    int Lv = 1;
    for (int i=9;i>=0;i--){
        int total = 16*Lv*64;
        recon_kernel<<<(total+255)/256,256>>>(vc, us+offs[i], ud+offs[i],
                                              rc_e, rc_o, vn, Lv, total);
        float* t=vc; vc=vn; vn=t;
        Lv <<= 1;
    }
    sgemm512<<<ggrid,256>>>(vc, out_w, out_b, outp);
}

// round 8
// speedup vs baseline: 1.7322x; 1.2831x over previous
#include <cuda_runtime.h>
#include <cuda_bf16.h>
#include <math.h>
#include <stdint.h>

// Problem constants
#define NB   16
#define NSEQ 1024
#define CK   512          // C*K

// -------- scratch (device globals; no allocation allowed) --------
__device__ float g_bufA[NB*NSEQ*CK];
__device__ float g_bufB[NB*NSEQ*CK];
__device__ float g_kA[NB*NSEQ*CK];
__device__ float g_kB[NB*NSEQ*CK];
__device__ float g_dq[NB*512*CK];
__device__ float g_dk[NB*512*CK];
__device__ float g_Us[NB*1023*CK];
__device__ float g_Ud[NB*1023*CK];
__device__ float g_S[NB*4*2*16*CK];   // spectra: (b, tensor{dq,dk,qn,kn}, re/im, mode, ck)
__device__ float g_O[NB*2*2*16*CK];   // post-attn spectra: (b, which{s,d}, re/im, mode, ck)
__device__ __nv_bfloat16 g_Ahi[NB*NSEQ*CK];
__device__ __nv_bfloat16 g_Alo[NB*NSEQ*CK];
__device__ __nv_bfloat16 g_Wthi[CK*CK];
__device__ __nv_bfloat16 g_Wtlo[CK*CK];

__device__ __forceinline__ uint32_t smem_u32(const void* p){
    uint32_t a;
    asm("{ .reg .u64 t; cvta.to.shared.u64 t, %1; cvt.u32.u64 %0, t; }" : "=r"(a) : "l"(p));
    return a;
}

// ================= bf16 split conversion kernels =================
__global__ __launch_bounds__(256) void convA_kernel(const float* __restrict__ x,
    __nv_bfloat16* __restrict__ hi, __nv_bfloat16* __restrict__ lo, int n4)
{
    int i = blockIdx.x*256 + threadIdx.x;
    if (i >= n4) return;
    float4 v = ((const float4*)x)[i];
    __nv_bfloat16 h0 = __float2bfloat16(v.x), h1 = __float2bfloat16(v.y);
    __nv_bfloat16 h2 = __float2bfloat16(v.z), h3 = __float2bfloat16(v.w);
    ((__nv_bfloat162*)hi)[2*i]   = __halves2bfloat162(h0, h1);
    ((__nv_bfloat162*)hi)[2*i+1] = __halves2bfloat162(h2, h3);
    __nv_bfloat16 l0 = __float2bfloat16(v.x - __bfloat162float(h0));
    __nv_bfloat16 l1 = __float2bfloat16(v.y - __bfloat162float(h1));
    __nv_bfloat16 l2 = __float2bfloat16(v.z - __bfloat162float(h2));
    __nv_bfloat16 l3 = __float2bfloat16(v.w - __bfloat162float(h3));
    ((__nv_bfloat162*)lo)[2*i]   = __halves2bfloat162(l0, l1);
    ((__nv_bfloat162*)lo)[2*i+1] = __halves2bfloat162(l2, l3);
}

// W fp32 [K=512, N=512] row-major -> Wt hi/lo bf16 [N=512, K=512] (transposed)
__global__ __launch_bounds__(256) void convW_kernel(const float* __restrict__ W,
    __nv_bfloat16* __restrict__ hi, __nv_bfloat16* __restrict__ lo)
{
    __shared__ float t[32][33];
    int bx = blockIdx.x, by = blockIdx.y;
    int tx = threadIdx.x & 31, ty = threadIdx.x >> 5;
    for (int i = ty; i < 32; i += 8)
        t[i][tx] = W[(size_t)(bx*32 + i)*512 + by*32 + tx];
    __syncthreads();
    for (int i = ty; i < 32; i += 8){
        float v = t[tx][i];
        __nv_bfloat16 h = __float2bfloat16(v);
        size_t o = (size_t)(by*32 + i)*512 + bx*32 + tx;
        hi[o] = h;
        lo[o] = __float2bfloat16(v - __bfloat162float(h));
    }
}

// ================= tensor-core GEMM via mma.sync (bf16 split, fp32 accum) =================
// C[M,512] = A[M,512] @ W[512,512] + bias,  A as (Ahi,Alo), W^T as (Bhi,Blo) [n][k]
// block tile 128x128, BK=32, 8 warps (2m x 4n), warp tile 64x32.
// smem per stage: 4 arrays x 128 rows x 40 halves (pad: 80B stride, conflict-free).
#define STAGE_BYTES 40960          // 4 * 128*40*2
#define ARR_BYTES   10240          // 128*40*2
#define GEMM_SMEM   (2*STAGE_BYTES)

__device__ __forceinline__ void mma16816(float* d, const uint32_t* a, const uint32_t* b){
    asm volatile(
        "mma.sync.aligned.m16n8k16.row.col.f32.bf16.bf16.f32 "
        "{%0,%1,%2,%3}, {%4,%5,%6,%7}, {%8,%9}, {%0,%1,%2,%3};"
        : "+f"(d[0]), "+f"(d[1]), "+f"(d[2]), "+f"(d[3])
        : "r"(a[0]), "r"(a[1]), "r"(a[2]), "r"(a[3]), "r"(b[0]), "r"(b[1]));
}

__device__ __forceinline__ void load_chunk(
    const __nv_bfloat16* __restrict__ Ahi, const __nv_bfloat16* __restrict__ Alo,
    const __nv_bfloat16* __restrict__ Bhi, const __nv_bfloat16* __restrict__ Blo,
    int m0, int n0, int k0, uint32_t sstage, int tid)
{
    const __nv_bfloat16* srcs[4] = {Ahi, Alo, Bhi, Blo};
    #pragma unroll
    for (int t = 0; t < 8; t++){
        const int arr = t >> 1;
        const int row = (t & 1)*64 + (tid >> 2);
        const int seg = tid & 3;
        const int rb  = (arr < 2) ? m0 : n0;
        const __nv_bfloat16* g = srcs[arr] + (size_t)(rb + row)*512 + k0 + seg*8;
        uint32_t d = sstage + arr*ARR_BYTES + row*80 + seg*16;
        asm volatile("cp.async.cg.shared.global [%0], [%1], 16;" :: "r"(d), "l"(g));
    }
}

__global__ __launch_bounds__(256) void gemm_mma(
    const __nv_bfloat16* __restrict__ Ahi, const __nv_bfloat16* __restrict__ Alo,
    const __nv_bfloat16* __restrict__ Bhi, const __nv_bfloat16* __restrict__ Blo,
    const float* __restrict__ bias, float* __restrict__ C)
{
    extern __shared__ char smem[];
    uint32_t sb = smem_u32(smem);
    const int tid  = threadIdx.x;
    const int lane = tid & 31, warp = tid >> 5;
    const int wm64 = (warp >> 2) * 64, wn32 = (warp & 3) * 32;
    const int grp  = lane >> 2,  q2   = (lane & 3) * 2;
    const int n0 = blockIdx.x * 128, m0 = blockIdx.y * 128;

    float acc[4][4][4];
    #pragma unroll
    for (int i=0;i<4;i++)
        #pragma unroll
        for (int j=0;j<4;j++)
            #pragma unroll
            for (int r=0;r<4;r++) acc[i][j][r]=0.f;

    load_chunk(Ahi, Alo, Bhi, Blo, m0, n0, 0,  sb,               tid);
    asm volatile("cp.async.commit_group;" ::: "memory");
    load_chunk(Ahi, Alo, Bhi, Blo, m0, n0, 32, sb + STAGE_BYTES, tid);
    asm volatile("cp.async.commit_group;" ::: "memory");

    for (int c = 0; c < 16; c++){
        if (c < 15) asm volatile("cp.async.wait_group 1;" ::: "memory");
        else        asm volatile("cp.async.wait_group 0;" ::: "memory");
        __syncthreads();

        const char* st = smem + (c & 1)*STAGE_BYTES;
        const __nv_bfloat16* sAhi = (const __nv_bfloat16*)(st);
        const __nv_bfloat16* sAlo = (const __nv_bfloat16*)(st + ARR_BYTES);
        const __nv_bfloat16* sBhi = (const __nv_bfloat16*)(st + 2*ARR_BYTES);
        const __nv_bfloat16* sBlo = (const __nv_bfloat16*)(st + 3*ARR_BYTES);

        #pragma unroll
        for (int pass = 0; pass < 3; pass++){
            const __nv_bfloat16* As = (pass == 1) ? sAlo : sAhi;
            const __nv_bfloat16* Bs = (pass == 2) ? sBlo : sBhi;
            #pragma unroll
            for (int ks = 0; ks < 2; ks++){
                const int col = ks*16 + q2;
                uint32_t af[4][4], bf[4][2];
                #pragma unroll
                for (int mt = 0; mt < 4; mt++){
                    int r = wm64 + mt*16 + grp;
                    af[mt][0] = *(const uint32_t*)(As + r*40     + col);
                    af[mt][1] = *(const uint32_t*)(As + (r+8)*40 + col);
                    af[mt][2] = *(const uint32_t*)(As + r*40     + col + 8);
                    af[mt][3] = *(const uint32_t*)(As + (r+8)*40 + col + 8);
                }
                #pragma unroll
                for (int nt = 0; nt < 4; nt++){
                    int n = wn32 + nt*8 + grp;
                    bf[nt][0] = *(const uint32_t*)(Bs + n*40 + col);
                    bf[nt][1] = *(const uint32_t*)(Bs + n*40 + col + 8);
                }
                #pragma unroll
                for (int mt = 0; mt < 4; mt++)
                    #pragma unroll
                    for (int nt = 0; nt < 4; nt++)
                        mma16816(acc[mt][nt], af[mt], bf[nt]);
            }
        }
        __syncthreads();
        if (c + 2 < 16){
            load_chunk(Ahi, Alo, Bhi, Blo, m0, n0, (c+2)*32,
                       sb + (c & 1)*STAGE_BYTES, tid);
            asm volatile("cp.async.commit_group;" ::: "memory");
        }
    }

    // epilogue: accum + bias -> C
    #pragma unroll
    for (int mt = 0; mt < 4; mt++){
        #pragma unroll
        for (int nt = 0; nt < 4; nt++){
            int r   = m0 + wm64 + mt*16 + grp;
            int col = n0 + wn32 + nt*8 + q2;
            float b0 = bias[col], b1 = bias[col+1];
            float2 v0 = make_float2(acc[mt][nt][0] + b0, acc[mt][nt][1] + b1);
            float2 v1 = make_float2(acc[mt][nt][2] + b0, acc[mt][nt][3] + b1);
            *(float2*)(C + (size_t)r*512 + col)     = v0;
            *(float2*)(C + (size_t)(r+8)*512 + col) = v1;
        }
    }
}

// ---------------- wavelet: x(b,2Lh,C,K) -> d,s (b,Lh,C,K) ----------------
__global__ __launch_bounds__(256) void wavelet_kernel(const float* __restrict__ x,
    float* __restrict__ d, float* __restrict__ s,
    const float* __restrict__ ecd, const float* __restrict__ ecs,
    int Lh, int total)
{
    __shared__ float wd[16][8], ws[16][8];
    int tid = threadIdx.x;
    if (tid < 128){ ((float*)wd)[tid] = ecd[tid]; ((float*)ws)[tid] = ecs[tid]; }
    __syncthreads();
    int idx = blockIdx.x*256 + tid;
    if (idx >= total) return;
    int c = idx & 63;
    int j = (idx >> 6) % Lh;
    int b = idx / (Lh << 6);
    const float* xe = x + (((size_t)b*(Lh<<1) + 2*j)*64 + c)*8;
    float xa[16];
    *(float4*)(xa)    = *(const float4*)(xe);
    *(float4*)(xa+4)  = *(const float4*)(xe+4);
    *(float4*)(xa+8)  = *(const float4*)(xe+512);
    *(float4*)(xa+12) = *(const float4*)(xe+516);
    float dv[8], sv[8];
    #pragma unroll
    for (int k=0;k<8;k++){ dv[k]=0.f; sv[k]=0.f; }
    #pragma unroll
    for (int t=0;t<16;t++){
        float xv = xa[t];
        #pragma unroll
        for (int k=0;k<8;k++){ dv[k] += xv*wd[t][k]; sv[k] += xv*ws[t][k]; }
    }
    float* dp = d + (size_t)idx*8;
    float* sp = s + (size_t)idx*8;
    *(float4*)(dp)   = make_float4(dv[0],dv[1],dv[2],dv[3]);
    *(float4*)(dp+4) = make_float4(dv[4],dv[5],dv[6],dv[7]);
    *(float4*)(sp)   = make_float4(sv[0],sv[1],sv[2],sv[3]);
    *(float4*)(sp+4) = make_float4(sv[4],sv[5],sv[6],sv[7]);
}

// ---------------- forward DFT ----------------
__global__ __launch_bounds__(256) void dft_kernel(
    const float* __restrict__ t0, const float* __restrict__ t1,
    const float* __restrict__ t2, const float* __restrict__ t3,
    float* __restrict__ S, int Lh, int m)
{
    __shared__ float twc[512], tws[512];
    const int tid = threadIdx.x;
    const int b = blockIdx.x, tensor = blockIdx.y, ck0 = blockIdx.z * 128;
    for (int r = tid; r < Lh; r += 256){
        float sv, cv;
        sincosf(6.283185307179586f * ((float)r / (float)Lh), &sv, &cv);
        twc[r]=cv; tws[r]=sv;
    }
    __syncthreads();
    const float* X = (tensor==0) ? t0 : (tensor==1) ? t1 : (tensor==2) ? t2 : t3;
    const int col = tid & 127;
    const int half = tid >> 7;
    const float* tw = half ? tws : twc;
    const float* p = X + (size_t)b*Lh*512 + ck0 + col;
    float acc[16];
    #pragma unroll
    for (int f=0; f<16; f++) acc[f]=0.f;
    #pragma unroll 2
    for (int l=0; l<Lh; l++){
        float xv = p[(size_t)l*512];
        int r = 0;
        #pragma unroll
        for (int f=0; f<16; f++){
            acc[f] += xv * tw[r];
            r += l; if (r >= Lh) r -= Lh;
        }
    }
    float sgn = half ? -1.0f : 1.0f;
    float* out = S + ((((size_t)b*4 + tensor)*2 + half)*16)*512 + ck0 + col;
    for (int f=0; f<m; f++)
        out[(size_t)f*512] = sgn * acc[f];
}

// ---------------- mid: QK = ctanh(Sq^T Sk); O = QK Sk^T ----------------
__global__ __launch_bounds__(256) void mid_kernel(const float* __restrict__ S,
    float* __restrict__ O, int m)
{
    __shared__ float Sqr[64][16], Sqi[64][16], Skr[64][16], Ski[64][16];
    __shared__ float QKr[16][17], QKi[16][17];
    const int tid = threadIdx.x;
    const int b = blockIdx.x >> 3, h = blockIdx.x & 7;
    const int which = blockIdx.y;

    const float* base = S + (size_t)(b*4 + which*2)*2*16*512;
    for (int idx = tid; idx < 64*16; idx += 256){
        int e = idx >> 4, f = idx & 15;
        size_t o = (size_t)f*512 + e*8 + h;
        Sqr[e][f] = base[o];
        Sqi[e][f] = base[o + 8192];
        Skr[e][f] = base[o + 16384];
        Ski[e][f] = base[o + 24576];
    }
    __syncthreads();

    if (tid < m*m){
        int x = tid / m, y = tid - x*m;
        float sr=0.f, sim=0.f;
        #pragma unroll 8
        for (int e=0;e<64;e++){
            float qr=Sqr[e][x], qi=Sqi[e][x];
            float kr=Skr[e][y], ki=Ski[e][y];
            sr  += qr*kr - qi*ki;
            sim += qr*ki + qi*kr;
        }
        float txx = tanhf(sr);
        float tyy = tanf(sim);
        float tx2=txx*txx, ty2=tyy*tyy;
        float den = 1.0f + tx2*ty2;
        QKr[x][y] = txx*(1.0f+ty2)/den;
        QKi[x][y] = tyy*(1.0f-tx2)/den;
    }
    __syncthreads();

    float* ob = O + (size_t)(b*2 + which)*2*16*512;
    for (int t = tid; t < 64*m; t += 256){
        int x = t % m, e = t / m;
        float orr=0.f, oii=0.f;
        for (int y=0;y<m;y++){
            float ar=QKr[x][y], ai2=QKi[x][y];
            float br=Skr[e][y], bi=Ski[e][y];
            orr += ar*br - ai2*bi;
            oii += ar*bi + ai2*br;
        }
        size_t o = (size_t)x*512 + e*8 + h;
        ob[o]        = orr;
        ob[o + 8192] = oii;
    }
}

// ---------------- inverse DFT + fused add ----------------
__global__ __launch_bounds__(256) void idft_kernel(const float* __restrict__ O,
    float* __restrict__ Us, float* __restrict__ Ud,
    int Lh, int m, float scale, int rows)
{
    __shared__ float twc[512], tws[512];
    __shared__ float Osm[2][2][16][128];
    const int tid = threadIdx.x;
    const int b = blockIdx.x, ck0 = blockIdx.y * 128;
    for (int r = tid; r < Lh; r += 256){
        float sv, cv;
        sincosf(6.283185307179586f * ((float)r / (float)Lh), &sv, &cv);
        twc[r]=cv; tws[r]=sv;
    }
    for (int idx = tid; idx < 2*2*16*128; idx += 256){
        int w    = idx >> 12;
        int rem  = idx & 4095;
        int reim = rem >> 11;
        int f    = (rem >> 7) & 15;
        int col  = rem & 127;
        Osm[w][reim][f][col] =
            O[(size_t)((b*2 + w)*2 + reim)*8192 + (size_t)f*512 + ck0 + col];
    }
    __syncthreads();
    const int l0 = blockIdx.z * rows;
    for (int t = tid; t < rows*128; t += 256){
        int lr = t >> 7, col = t & 127;
        int l = l0 + lr;
        float as = Osm[0][0][0][col];
        float ad = Osm[1][0][0][col];
        int r = 0;
        for (int f=1; f<m; f++){
            r += l; if (r >= Lh) r -= Lh;
            float c = twc[r], s = tws[r];
            as += 2.0f*(Osm[0][0][f][col]*c - Osm[0][1][f][col]*s);
            ad += 2.0f*(Osm[1][0][f][col]*c - Osm[1][1][f][col]*s);
        }
        size_t oi = ((size_t)b*Lh + l)*512 + ck0 + col;
        float usv = as * scale;
        Us[oi] = usv;
        Ud[oi] = ad * scale + usv;
    }
}

// ---------------- reconstruction ----------------
__global__ __launch_bounds__(256) void recon_kernel(const float* __restrict__ v,
    const float* __restrict__ Us, const float* __restrict__ Ud,
    const float* __restrict__ rce, const float* __restrict__ rco,
    float* __restrict__ outv, int Lv, int total)
{
    __shared__ float we[16][8], wo[16][8];
    int tid = threadIdx.x;
    if (tid < 128){ ((float*)we)[tid] = rce[tid]; ((float*)wo)[tid] = rco[tid]; }
    __syncthreads();
    int idx = blockIdx.x*256 + tid;
    if (idx >= total) return;
    int c = idx & 63;
    int l = (idx >> 6) % Lv;
    int b = idx / (Lv << 6);
    const float* vp = v  + (size_t)idx*8;
    const float* up = Us + (size_t)idx*8;
    const float* dp = Ud + (size_t)idx*8;
    float w[16];
    #pragma unroll
    for (int t=0;t<8;t++) w[t]   = vp[t] + up[t];
    #pragma unroll
    for (int t=0;t<8;t++) w[8+t] = dp[t];
    float ev[8], ov[8];
    #pragma unroll
    for (int k=0;k<8;k++){ ev[k]=0.f; ov[k]=0.f; }
    #pragma unroll
    for (int t=0;t<16;t++){
        float xv = w[t];
        #pragma unroll
        for (int k=0;k<8;k++){ ev[k] += xv*we[t][k]; ov[k] += xv*wo[t][k]; }
    }
    float* op = outv + (((size_t)b*(Lv<<1) + 2*l)*64 + c)*8;
    *(float4*)(op)     = make_float4(ev[0],ev[1],ev[2],ev[3]);
    *(float4*)(op+4)   = make_float4(ev[4],ev[5],ev[6],ev[7]);
    *(float4*)(op+512) = make_float4(ov[0],ov[1],ov[2],ov[3]);
    *(float4*)(op+516) = make_float4(ov[4],ov[5],ov[6],ov[7]);
}

__global__ void zero_kernel(float* p, int n){
    int i = blockIdx.x*blockDim.x + threadIdx.x;
    if (i < n) p[i] = 0.f;
}

// ---------------- orchestration ----------------
extern "C" void kernel_launch(void* const* d_in, const int* in_sizes, int n_in,
                              void* d_out, int out_size)
{
    (void)in_sizes; (void)n_in; (void)out_size;
    const float* q     = (const float*)d_in[0];
    const float* k     = (const float*)d_in[1];
    // d_in[2] (v), d_in[7] (Lv_w), d_in[8] (Lv_b) provably unused by the math
    const float* Lq_w  = (const float*)d_in[3];
    const float* Lq_b  = (const float*)d_in[4];
    const float* Lk_w  = (const float*)d_in[5];
    const float* Lk_b  = (const float*)d_in[6];
    const float* out_w = (const float*)d_in[9];
    const float* out_b = (const float*)d_in[10];
    const float* ec_s  = (const float*)d_in[11];
    const float* ec_d  = (const float*)d_in[12];
    const float* rc_e  = (const float*)d_in[13];
    const float* rc_o  = (const float*)d_in[14];
    float* outp = (float*)d_out;

    float *bufA,*bufB,*kA,*kB,*dq,*dk,*us,*ud,*S,*O;
    __nv_bfloat16 *Ahi,*Alo,*Wthi,*Wtlo;
    cudaGetSymbolAddress((void**)&bufA, g_bufA);
    cudaGetSymbolAddress((void**)&bufB, g_bufB);
    cudaGetSymbolAddress((void**)&kA,   g_kA);
    cudaGetSymbolAddress((void**)&kB,   g_kB);
    cudaGetSymbolAddress((void**)&dq,   g_dq);
    cudaGetSymbolAddress((void**)&dk,   g_dk);
    cudaGetSymbolAddress((void**)&us,   g_Us);
    cudaGetSymbolAddress((void**)&ud,   g_Ud);
    cudaGetSymbolAddress((void**)&S,    g_S);
    cudaGetSymbolAddress((void**)&O,    g_O);
    cudaGetSymbolAddress((void**)&Ahi,  g_Ahi);
    cudaGetSymbolAddress((void**)&Alo,  g_Alo);
    cudaGetSymbolAddress((void**)&Wthi, g_Wthi);
    cudaGetSymbolAddress((void**)&Wtlo, g_Wtlo);

    cudaFuncSetAttribute(gemm_mma, cudaFuncAttributeMaxDynamicSharedMemorySize, GEMM_SMEM);

    const int nA4 = NB*NSEQ*CK/4;   // float4 count for A conversions
    dim3 gW(16,16);
    dim3 gG(4,128);

    // GEMM 1: bufA = q @ Lq_w + Lq_b
    convW_kernel<<<gW,256>>>(Lq_w, Wthi, Wtlo);
    convA_kernel<<<(nA4+255)/256,256>>>(q, Ahi, Alo, nA4);
    gemm_mma<<<gG,256,GEMM_SMEM>>>(Ahi, Alo, Wthi, Wtlo, Lq_b, bufA);

    // GEMM 2: kA = k @ Lk_w + Lk_b
    convW_kernel<<<gW,256>>>(Lk_w, Wthi, Wtlo);
    convA_kernel<<<(nA4+255)/256,256>>>(k, Ahi, Alo, nA4);
    gemm_mma<<<gG,256,GEMM_SMEM>>>(Ahi, Alo, Wthi, Wtlo, Lk_b, kA);

    float *qc=bufA,*qn=bufB,*kc=kA,*kn=kB;
    size_t offs[10]; size_t off=0;
    int L = 1024;
    for (int i=0;i<10;i++){
        int Lh = L >> 1;
        int m  = (Lh>>1) < 16 ? (Lh>>1) : 16;
        if (m > 0){
            int total = 16*Lh*64;
            int blocks = (total + 255)/256;
            wavelet_kernel<<<blocks,256>>>(qc, dq, qn, ec_d, ec_s, Lh, total);
            wavelet_kernel<<<blocks,256>>>(kc, dk, kn, ec_d, ec_s, Lh, total);
            dft_kernel<<<dim3(16,4,4),256>>>(dq, dk, qn, kn, S, Lh, m);
            mid_kernel<<<dim3(128,2),256>>>(S, O, m);
            float inv_scale = 1.0f/(4096.0f*(float)Lh);
            int lsplit = (Lh >= 64) ? (Lh/64) : 1;
            int rows   = Lh / lsplit;
            idft_kernel<<<dim3(16,4,lsplit),256>>>(O, us+off, ud+off, Lh, m, inv_scale, rows);
        } else {
            zero_kernel<<<32,256>>>(us+off, 16*1*512);
            zero_kernel<<<32,256>>>(ud+off, 16*1*512);
        }
        offs[i] = off; off += (size_t)16*Lh*512;
        float* t; t=qc; qc=qn; qn=t;  t=kc; kc=kn; kn=t;
        L = Lh;
    }

    // v = FCA at L=1 = zeros; reconstruct upward
    float *vc=bufA, *vn=bufB;
    zero_kernel<<<32,256>>>(vc, 16*1*512);
    int Lv = 1;
    for (int i=9;i>=0;i--){
        int total = 16*Lv*64;
        recon_kernel<<<(total+255)/256,256>>>(vc, us+offs[i], ud+offs[i],
                                              rc_e, rc_o, vn, Lv, total);
        float* t=vc; vc=vn; vn=t;
        Lv <<= 1;
    }

    // GEMM 3: out = vc @ out_w + out_b
    convW_kernel<<<gW,256>>>(out_w, Wthi, Wtlo);
    convA_kernel<<<(nA4+255)/256,256>>>(vc, Ahi, Alo, nA4);
    gemm_mma<<<gG,256,GEMM_SMEM>>>(Ahi, Alo, Wthi, Wtlo, out_b, outp);
}

// round 9
// speedup vs baseline: 1.7560x; 1.0137x over previous
#include <cuda_runtime.h>
#include <cuda_bf16.h>
#include <math.h>
#include <stdint.h>

// Problem constants
#define NB   16
#define NSEQ 1024
#define CK   512          // C*K

// -------- scratch (device globals; no allocation allowed) --------
__device__ float g_bufA[NB*NSEQ*CK];
__device__ float g_bufB[NB*NSEQ*CK];
__device__ float g_kA[NB*NSEQ*CK];
__device__ float g_kB[NB*NSEQ*CK];
__device__ float g_dq[NB*512*CK];
__device__ float g_dk[NB*512*CK];
__device__ float g_Us[NB*1023*CK];
__device__ float g_Ud[NB*1023*CK];
__device__ float g_S[NB*4*2*16*CK];   // spectra: (b, tensor{dq,dk,qn,kn}, re/im, mode, ck)
__device__ float g_O[NB*2*2*16*CK];   // post-attn spectra: (b, which{s,d}, re/im, mode, ck)
__device__ __nv_bfloat16 g_Wthi[CK*CK];
__device__ __nv_bfloat16 g_Wtlo[CK*CK];
__device__ __nv_bfloat16 g_W2hi[CK*CK];
__device__ __nv_bfloat16 g_W2lo[CK*CK];

__device__ __forceinline__ uint32_t smem_u32(const void* p){
    uint32_t a;
    asm("{ .reg .u64 t; cvta.to.shared.u64 t, %1; cvt.u32.u64 %0, t; }" : "=r"(a) : "l"(p));
    return a;
}

// W fp32 [K=512, N=512] row-major -> Wt hi/lo bf16 [N=512, K=512] (transposed)
__global__ __launch_bounds__(256) void convW_kernel(const float* __restrict__ W,
    __nv_bfloat16* __restrict__ hi, __nv_bfloat16* __restrict__ lo)
{
    __shared__ float t[32][33];
    int bx = blockIdx.x, by = blockIdx.y;
    int tx = threadIdx.x & 31, ty = threadIdx.x >> 5;
    for (int i = ty; i < 32; i += 8)
        t[i][tx] = W[(size_t)(bx*32 + i)*512 + by*32 + tx];
    __syncthreads();
    for (int i = ty; i < 32; i += 8){
        float v = t[tx][i];
        __nv_bfloat16 h = __float2bfloat16(v);
        size_t o = (size_t)(by*32 + i)*512 + bx*32 + tx;
        hi[o] = h;
        lo[o] = __float2bfloat16(v - __bfloat162float(h));
    }
}

// ================= tensor-core GEMM via mma.sync (bf16 split, fp32 accum) =================
// C[M,512] = A[M,512] @ W[512,512] + bias.  A read as fp32 and split in-kernel;
// W^T pre-split as (Bhi,Blo) [n][k] bf16.
// block tile 128x128, BK=32, 8 warps (2m x 4n), warp tile 64x32.
// smem per stage: 4 arrays x 128 rows x 40 halves (pad: 80B stride, conflict-free).
#define STAGE_BYTES 40960          // 4 * 128*40*2
#define ARR_BYTES   10240          // 128*40*2
#define GEMM_SMEM   (2*STAGE_BYTES)

__device__ __forceinline__ void mma16816(float* d, const uint32_t* a, const uint32_t* b){
    asm volatile(
        "mma.sync.aligned.m16n8k16.row.col.f32.bf16.bf16.f32 "
        "{%0,%1,%2,%3}, {%4,%5,%6,%7}, {%8,%9}, {%0,%1,%2,%3};"
        : "+f"(d[0]), "+f"(d[1]), "+f"(d[2]), "+f"(d[3])
        : "r"(a[0]), "r"(a[1]), "r"(a[2]), "r"(a[3]), "r"(b[0]), "r"(b[1]));
}

// B (Wthi/Wtlo) staging via cp.async, 2 stages ahead (arrays 2,3 of the stage)
__device__ __forceinline__ void loadB_async(
    const __nv_bfloat16* __restrict__ Bhi, const __nv_bfloat16* __restrict__ Blo,
    int n0, int k0, uint32_t sstage, int tid)
{
    #pragma unroll
    for (int t = 4; t < 8; t++){
        const int arr = t >> 1;                 // 2 or 3
        const int row = (t & 1)*64 + (tid >> 2);
        const int seg = tid & 3;
        const __nv_bfloat16* g = ((arr == 2) ? Bhi : Blo) + (size_t)(n0 + row)*512 + k0 + seg*8;
        uint32_t d = sstage + arr*ARR_BYTES + row*80 + seg*16;
        asm volatile("cp.async.cg.shared.global [%0], [%1], 16;" :: "r"(d), "l"(g));
    }
}

// A fp32 chunk prefetch into regs: 2 tasks/thread, each 8 consecutive floats
__device__ __forceinline__ void prefetchA(const float* __restrict__ A,
    int m0, int k0, int tid, float4* pa)
{
    #pragma unroll
    for (int t = 0; t < 2; t++){
        int idx = tid + t*256;
        int row = idx >> 2, seg = idx & 3;
        const float* g = A + (size_t)(m0 + row)*512 + k0 + seg*8;
        pa[2*t]   = *(const float4*)g;
        pa[2*t+1] = *(const float4*)(g + 4);
    }
}

__device__ __forceinline__ uint32_t pack2(__nv_bfloat16 a, __nv_bfloat16 b){
    __nv_bfloat162 h; h.x = a; h.y = b;
    return *(uint32_t*)&h;
}

// convert prefetched A regs to hi/lo bf16 and store to stage (arrays 0,1)
__device__ __forceinline__ void stsA(uint32_t sstage, int tid, const float4* pa){
    #pragma unroll
    for (int t = 0; t < 2; t++){
        int idx = tid + t*256;
        int row = idx >> 2, seg = idx & 3;
        float4 v0 = pa[2*t], v1 = pa[2*t+1];
        __nv_bfloat16 h0 = __float2bfloat16(v0.x), h1 = __float2bfloat16(v0.y);
        __nv_bfloat16 h2 = __float2bfloat16(v0.z), h3 = __float2bfloat16(v0.w);
        __nv_bfloat16 h4 = __float2bfloat16(v1.x), h5 = __float2bfloat16(v1.y);
        __nv_bfloat16 h6 = __float2bfloat16(v1.z), h7 = __float2bfloat16(v1.w);
        uint4 hv;
        hv.x = pack2(h0, h1); hv.y = pack2(h2, h3);
        hv.z = pack2(h4, h5); hv.w = pack2(h6, h7);
        uint4 lv;
        lv.x = pack2(__float2bfloat16(v0.x - __bfloat162float(h0)),
                     __float2bfloat16(v0.y - __bfloat162float(h1)));
        lv.y = pack2(__float2bfloat16(v0.z - __bfloat162float(h2)),
                     __float2bfloat16(v0.w - __bfloat162float(h3)));
        lv.z = pack2(__float2bfloat16(v1.x - __bfloat162float(h4)),
                     __float2bfloat16(v1.y - __bfloat162float(h5)));
        lv.w = pack2(__float2bfloat16(v1.z - __bfloat162float(h6)),
                     __float2bfloat16(v1.w - __bfloat162float(h7)));
        uint32_t dhi = sstage + row*80 + seg*16;
        asm volatile("st.shared.v4.b32 [%0], {%1,%2,%3,%4};"
                     :: "r"(dhi), "r"(hv.x), "r"(hv.y), "r"(hv.z), "r"(hv.w) : "memory");
        asm volatile("st.shared.v4.b32 [%0], {%1,%2,%3,%4};"
                     :: "r"(dhi + ARR_BYTES), "r"(lv.x), "r"(lv.y), "r"(lv.z), "r"(lv.w) : "memory");
    }
}

__global__ __launch_bounds__(256,2) void gemm_mma(
    const float* __restrict__ A,
    const __nv_bfloat16* __restrict__ Bhi, const __nv_bfloat16* __restrict__ Blo,
    const float* __restrict__ bias, float* __restrict__ C)
{
    extern __shared__ char smem[];
    uint32_t sb = smem_u32(smem);
    const int tid  = threadIdx.x;
    const int lane = tid & 31, warp = tid >> 5;
    const int wm64 = (warp >> 2) * 64, wn32 = (warp & 3) * 32;
    const int grp  = lane >> 2,  q2   = (lane & 3) * 2;
    const int n0 = blockIdx.x * 128, m0 = blockIdx.y * 128;

    float acc[4][4][4];
    #pragma unroll
    for (int i=0;i<4;i++)
        #pragma unroll
        for (int j=0;j<4;j++)
            #pragma unroll
            for (int r=0;r<4;r++) acc[i][j][r]=0.f;

    float4 pa[4];
    // prologue: stage chunks 0,1; prefetch chunk 2 into regs
    prefetchA(A, m0, 0, tid, pa);
    loadB_async(Bhi, Blo, n0, 0, sb, tid);
    asm volatile("cp.async.commit_group;" ::: "memory");
    stsA(sb, tid, pa);
    prefetchA(A, m0, 32, tid, pa);
    loadB_async(Bhi, Blo, n0, 32, sb + STAGE_BYTES, tid);
    asm volatile("cp.async.commit_group;" ::: "memory");
    stsA(sb + STAGE_BYTES, tid, pa);
    prefetchA(A, m0, 64, tid, pa);

    for (int c = 0; c < 16; c++){
        if (c < 15) asm volatile("cp.async.wait_group 1;" ::: "memory");
        else        asm volatile("cp.async.wait_group 0;" ::: "memory");
        __syncthreads();

        const char* st = smem + (c & 1)*STAGE_BYTES;
        const __nv_bfloat16* sAhi = (const __nv_bfloat16*)(st);
        const __nv_bfloat16* sAlo = (const __nv_bfloat16*)(st + ARR_BYTES);
        const __nv_bfloat16* sBhi = (const __nv_bfloat16*)(st + 2*ARR_BYTES);
        const __nv_bfloat16* sBlo = (const __nv_bfloat16*)(st + 3*ARR_BYTES);

        #pragma unroll
        for (int pass = 0; pass < 3; pass++){
            const __nv_bfloat16* As = (pass == 1) ? sAlo : sAhi;
            const __nv_bfloat16* Bs = (pass == 2) ? sBlo : sBhi;
            #pragma unroll
            for (int ks = 0; ks < 2; ks++){
                const int col = ks*16 + q2;
                uint32_t af[4][4], bf[4][2];
                #pragma unroll
                for (int mt = 0; mt < 4; mt++){
                    int r = wm64 + mt*16 + grp;
                    af[mt][0] = *(const uint32_t*)(As + r*40     + col);
                    af[mt][1] = *(const uint32_t*)(As + (r+8)*40 + col);
                    af[mt][2] = *(const uint32_t*)(As + r*40     + col + 8);
                    af[mt][3] = *(const uint32_t*)(As + (r+8)*40 + col + 8);
                }
                #pragma unroll
                for (int nt = 0; nt < 4; nt++){
                    int n = wn32 + nt*8 + grp;
                    bf[nt][0] = *(const uint32_t*)(Bs + n*40 + col);
                    bf[nt][1] = *(const uint32_t*)(Bs + n*40 + col + 8);
                }
                #pragma unroll
                for (int mt = 0; mt < 4; mt++)
                    #pragma unroll
                    for (int nt = 0; nt < 4; nt++)
                        mma16816(acc[mt][nt], af[mt], bf[nt]);
            }
        }
        __syncthreads();
        if (c + 2 < 16){
            uint32_t dst = sb + (c & 1)*STAGE_BYTES;
            loadB_async(Bhi, Blo, n0, (c+2)*32, dst, tid);
            asm volatile("cp.async.commit_group;" ::: "memory");
            stsA(dst, tid, pa);
            if (c + 3 < 16) prefetchA(A, m0, (c+3)*32, tid, pa);
        }
    }

    // epilogue: accum + bias -> C
    #pragma unroll
    for (int mt = 0; mt < 4; mt++){
        #pragma unroll
        for (int nt = 0; nt < 4; nt++){
            int r   = m0 + wm64 + mt*16 + grp;
            int col = n0 + wn32 + nt*8 + q2;
            float b0 = bias[col], b1 = bias[col+1];
            float2 v0 = make_float2(acc[mt][nt][0] + b0, acc[mt][nt][1] + b1);
            float2 v1 = make_float2(acc[mt][nt][2] + b0, acc[mt][nt][3] + b1);
            *(float2*)(C + (size_t)r*512 + col)     = v0;
            *(float2*)(C + (size_t)(r+8)*512 + col) = v1;
        }
    }
}

// ---------------- wavelet: x(b,2Lh,C,K) -> d,s (b,Lh,C,K) ----------------
__global__ __launch_bounds__(256) void wavelet_kernel(const float* __restrict__ x,
    float* __restrict__ d, float* __restrict__ s,
    const float* __restrict__ ecd, const float* __restrict__ ecs,
    int Lh, int total)
{
    __shared__ float wd[16][8], ws[16][8];
    int tid = threadIdx.x;
    if (tid < 128){ ((float*)wd)[tid] = ecd[tid]; ((float*)ws)[tid] = ecs[tid]; }
    __syncthreads();
    int idx = blockIdx.x*256 + tid;
    if (idx >= total) return;
    int c = idx & 63;
    int j = (idx >> 6) % Lh;
    int b = idx / (Lh << 6);
    const float* xe = x + (((size_t)b*(Lh<<1) + 2*j)*64 + c)*8;
    float xa[16];
    *(float4*)(xa)    = *(const float4*)(xe);
    *(float4*)(xa+4)  = *(const float4*)(xe+4);
    *(float4*)(xa+8)  = *(const float4*)(xe+512);
    *(float4*)(xa+12) = *(const float4*)(xe+516);
    float dv[8], sv[8];
    #pragma unroll
    for (int k=0;k<8;k++){ dv[k]=0.f; sv[k]=0.f; }
    #pragma unroll
    for (int t=0;t<16;t++){
        float xv = xa[t];
        #pragma unroll
        for (int k=0;k<8;k++){ dv[k] += xv*wd[t][k]; sv[k] += xv*ws[t][k]; }
    }
    float* dp = d + (size_t)idx*8;
    float* sp = s + (size_t)idx*8;
    *(float4*)(dp)   = make_float4(dv[0],dv[1],dv[2],dv[3]);
    *(float4*)(dp+4) = make_float4(dv[4],dv[5],dv[6],dv[7]);
    *(float4*)(sp)   = make_float4(sv[0],sv[1],sv[2],sv[3]);
    *(float4*)(sp+4) = make_float4(sv[4],sv[5],sv[6],sv[7]);
}

// ---------------- forward DFT ----------------
__global__ __launch_bounds__(256) void dft_kernel(
    const float* __restrict__ t0, const float* __restrict__ t1,
    const float* __restrict__ t2, const float* __restrict__ t3,
    float* __restrict__ S, int Lh, int m)
{
    __shared__ float twc[512], tws[512];
    const int tid = threadIdx.x;
    const int b = blockIdx.x, tensor = blockIdx.y, ck0 = blockIdx.z * 128;
    for (int r = tid; r < Lh; r += 256){
        float sv, cv;
        sincosf(6.283185307179586f * ((float)r / (float)Lh), &sv, &cv);
        twc[r]=cv; tws[r]=sv;
    }
    __syncthreads();
    const float* X = (tensor==0) ? t0 : (tensor==1) ? t1 : (tensor==2) ? t2 : t3;
    const int col = tid & 127;
    const int half = tid >> 7;
    const float* tw = half ? tws : twc;
    const float* p = X + (size_t)b*Lh*512 + ck0 + col;
    float acc[16];
    #pragma unroll
    for (int f=0; f<16; f++) acc[f]=0.f;
    #pragma unroll 2
    for (int l=0; l<Lh; l++){
        float xv = p[(size_t)l*512];
        int r = 0;
        #pragma unroll
        for (int f=0; f<16; f++){
            acc[f] += xv * tw[r];
            r += l; if (r >= Lh) r -= Lh;
        }
    }
    float sgn = half ? -1.0f : 1.0f;
    float* out = S + ((((size_t)b*4 + tensor)*2 + half)*16)*512 + ck0 + col;
    for (int f=0; f<m; f++)
        out[(size_t)f*512] = sgn * acc[f];
}

// ---------------- mid: QK = ctanh(Sq^T Sk); O = QK Sk^T ----------------
__global__ __launch_bounds__(256) void mid_kernel(const float* __restrict__ S,
    float* __restrict__ O, int m)
{
    __shared__ float Sqr[64][16], Sqi[64][16], Skr[64][16], Ski[64][16];
    __shared__ float QKr[16][17], QKi[16][17];
    const int tid = threadIdx.x;
    const int b = blockIdx.x >> 3, h = blockIdx.x & 7;
    const int which = blockIdx.y;

    const float* base = S + (size_t)(b*4 + which*2)*2*16*512;
    for (int idx = tid; idx < 64*16; idx += 256){
        int e = idx >> 4, f = idx & 15;
        size_t o = (size_t)f*512 + e*8 + h;
        Sqr[e][f] = base[o];
        Sqi[e][f] = base[o + 8192];
        Skr[e][f] = base[o + 16384];
        Ski[e][f] = base[o + 24576];
    }
    __syncthreads();

    if (tid < m*m){
        int x = tid / m, y = tid - x*m;
        float sr=0.f, sim=0.f;
        #pragma unroll 8
        for (int e=0;e<64;e++){
            float qr=Sqr[e][x], qi=Sqi[e][x];
            float kr=Skr[e][y], ki=Ski[e][y];
            sr  += qr*kr - qi*ki;
            sim += qr*ki + qi*kr;
        }
        float txx = tanhf(sr);
        float tyy = tanf(sim);
        float tx2=txx*txx, ty2=tyy*tyy;
        float den = 1.0f + tx2*ty2;
        QKr[x][y] = txx*(1.0f+ty2)/den;
        QKi[x][y] = tyy*(1.0f-tx2)/den;
    }
    __syncthreads();

    float* ob = O + (size_t)(b*2 + which)*2*16*512;
    for (int t = tid; t < 64*m; t += 256){
        int x = t % m, e = t / m;
        float orr=0.f, oii=0.f;
        for (int y=0;y<m;y++){
            float ar=QKr[x][y], ai2=QKi[x][y];
            float br=Skr[e][y], bi=Ski[e][y];
            orr += ar*br - ai2*bi;
            oii += ar*bi + ai2*br;
        }
        size_t o = (size_t)x*512 + e*8 + h;
        ob[o]        = orr;
        ob[o + 8192] = oii;
    }
}

// ---------------- inverse DFT + fused add ----------------
__global__ __launch_bounds__(256) void idft_kernel(const float* __restrict__ O,
    float* __restrict__ Us, float* __restrict__ Ud,
    int Lh, int m, float scale, int rows)
{
    __shared__ float twc[512], tws[512];
    __shared__ float Osm[2][2][16][128];
    const int tid = threadIdx.x;
    const int b = blockIdx.x, ck0 = blockIdx.y * 128;
    for (int r = tid; r < Lh; r += 256){
        float sv, cv;
        sincosf(6.283185307179586f * ((float)r / (float)Lh), &sv, &cv);
        twc[r]=cv; tws[r]=sv;
    }
    for (int idx = tid; idx < 2*2*16*128; idx += 256){
        int w    = idx >> 12;
        int rem  = idx & 4095;
        int reim = rem >> 11;
        int f    = (rem >> 7) & 15;
        int col  = rem & 127;
        Osm[w][reim][f][col] =
            O[(size_t)((b*2 + w)*2 + reim)*8192 + (size_t)f*512 + ck0 + col];
    }
    __syncthreads();
    const int l0 = blockIdx.z * rows;
    for (int t = tid; t < rows*128; t += 256){
        int lr = t >> 7, col = t & 127;
        int l = l0 + lr;
        float as = Osm[0][0][0][col];
        float ad = Osm[1][0][0][col];
        int r = 0;
        for (int f=1; f<m; f++){
            r += l; if (r >= Lh) r -= Lh;
            float c = twc[r], s = tws[r];
            as += 2.0f*(Osm[0][0][f][col]*c - Osm[0][1][f][col]*s);
            ad += 2.0f*(Osm[1][0][f][col]*c - Osm[1][1][f][col]*s);
        }
        size_t oi = ((size_t)b*Lh + l)*512 + ck0 + col;
        float usv = as * scale;
        Us[oi] = usv;
        Ud[oi] = ad * scale + usv;
    }
}

// ---------------- reconstruction ----------------
__global__ __launch_bounds__(256) void recon_kernel(const float* __restrict__ v,
    const float* __restrict__ Us, const float* __restrict__ Ud,
    const float* __restrict__ rce, const float* __restrict__ rco,
    float* __restrict__ outv, int Lv, int total)
{
    __shared__ float we[16][8], wo[16][8];
    int tid = threadIdx.x;
    if (tid < 128){ ((float*)we)[tid] = rce[tid]; ((float*)wo)[tid] = rco[tid]; }
    __syncthreads();
    int idx = blockIdx.x*256 + tid;
    if (idx >= total) return;
    int c = idx & 63;
    int l = (idx >> 6) % Lv;
    int b = idx / (Lv << 6);
    const float* vp = v  + (size_t)idx*8;
    const float* up = Us + (size_t)idx*8;
    const float* dp = Ud + (size_t)idx*8;
    float w[16];
    #pragma unroll
    for (int t=0;t<8;t++) w[t]   = vp[t] + up[t];
    #pragma unroll
    for (int t=0;t<8;t++) w[8+t] = dp[t];
    float ev[8], ov[8];
    #pragma unroll
    for (int k=0;k<8;k++){ ev[k]=0.f; ov[k]=0.f; }
    #pragma unroll
    for (int t=0;t<16;t++){
        float xv = w[t];
        #pragma unroll
        for (int k=0;k<8;k++){ ev[k] += xv*we[t][k]; ov[k] += xv*wo[t][k]; }
    }
    float* op = outv + (((size_t)b*(Lv<<1) + 2*l)*64 + c)*8;
    *(float4*)(op)     = make_float4(ev[0],ev[1],ev[2],ev[3]);
    *(float4*)(op+4)   = make_float4(ev[4],ev[5],ev[6],ev[7]);
    *(float4*)(op+512) = make_float4(ov[0],ov[1],ov[2],ov[3]);
    *(float4*)(op+516) = make_float4(ov[4],ov[5],ov[6],ov[7]);
}

__global__ void zero_kernel(float* p, int n){
    int i = blockIdx.x*blockDim.x + threadIdx.x;
    if (i < n) p[i] = 0.f;
}

// ---------------- orchestration ----------------
extern "C" void kernel_launch(void* const* d_in, const int* in_sizes, int n_in,
                              void* d_out, int out_size)
{
    (void)in_sizes; (void)n_in; (void)out_size;
    const float* q     = (const float*)d_in[0];
    const float* k     = (const float*)d_in[1];
    // d_in[2] (v), d_in[7] (Lv_w), d_in[8] (Lv_b) provably unused by the math
    const float* Lq_w  = (const float*)d_in[3];
    const float* Lq_b  = (const float*)d_in[4];
    const float* Lk_w  = (const float*)d_in[5];
    const float* Lk_b  = (const float*)d_in[6];
    const float* out_w = (const float*)d_in[9];
    const float* out_b = (const float*)d_in[10];
    const float* ec_s  = (const float*)d_in[11];
    const float* ec_d  = (const float*)d_in[12];
    const float* rc_e  = (const float*)d_in[13];
    const float* rc_o  = (const float*)d_in[14];
    float* outp = (float*)d_out;

    float *bufA,*bufB,*kA,*kB,*dq,*dk,*us,*ud,*S,*O;
    __nv_bfloat16 *Wthi,*Wtlo,*W2hi,*W2lo;
    cudaGetSymbolAddress((void**)&bufA, g_bufA);
    cudaGetSymbolAddress((void**)&bufB, g_bufB);
    cudaGetSymbolAddress((void**)&kA,   g_kA);
    cudaGetSymbolAddress((void**)&kB,   g_kB);
    cudaGetSymbolAddress((void**)&dq,   g_dq);
    cudaGetSymbolAddress((void**)&dk,   g_dk);
    cudaGetSymbolAddress((void**)&us,   g_Us);
    cudaGetSymbolAddress((void**)&ud,   g_Ud);
    cudaGetSymbolAddress((void**)&S,    g_S);
    cudaGetSymbolAddress((void**)&O,    g_O);
    cudaGetSymbolAddress((void**)&Wthi, g_Wthi);
    cudaGetSymbolAddress((void**)&Wtlo, g_Wtlo);
    cudaGetSymbolAddress((void**)&W2hi, g_W2hi);
    cudaGetSymbolAddress((void**)&W2lo, g_W2lo);

    cudaFuncSetAttribute(gemm_mma, cudaFuncAttributeMaxDynamicSharedMemorySize, GEMM_SMEM);

    dim3 gW(16,16);
    dim3 gG(4,128);

    // precompute level offsets
    size_t offs[10]; size_t off=0;
    { int L = 1024;
      for (int i=0;i<10;i++){ int Lh = L >> 1; offs[i] = off; off += (size_t)16*Lh*512; L = Lh; } }

    // level-9 (Lh==1, m=0) outputs are zero; launch up-front (also positions
    // gemm_mma as launch #6 for the ncu -s 5 -c 1 capture)
    zero_kernel<<<32,256>>>(us+offs[9], 16*1*512);
    zero_kernel<<<32,256>>>(ud+offs[9], 16*1*512);

    // GEMM 1 & 2: projections (A-side fp32->bf16 split fused into gemm)
    convW_kernel<<<gW,256>>>(Lq_w, Wthi, Wtlo);
    convW_kernel<<<gW,256>>>(Lk_w, W2hi, W2lo);
    gemm_mma<<<gG,256,GEMM_SMEM>>>(q, Wthi, Wtlo, Lq_b, bufA);
    gemm_mma<<<gG,256,GEMM_SMEM>>>(k, W2hi, W2lo, Lk_b, kA);

    float *qc=bufA,*qn=bufB,*kc=kA,*kn=kB;
    int L = 1024;
    for (int i=0;i<9;i++){
        int Lh = L >> 1;
        int m  = (Lh>>1) < 16 ? (Lh>>1) : 16;
        int total = 16*Lh*64;
        int blocks = (total + 255)/256;
        wavelet_kernel<<<blocks,256>>>(qc, dq, qn, ec_d, ec_s, Lh, total);
        wavelet_kernel<<<blocks,256>>>(kc, dk, kn, ec_d, ec_s, Lh, total);
        dft_kernel<<<dim3(16,4,4),256>>>(dq, dk, qn, kn, S, Lh, m);
        mid_kernel<<<dim3(128,2),256>>>(S, O, m);
        float inv_scale = 1.0f/(4096.0f*(float)Lh);
        int lsplit = (Lh >= 64) ? (Lh/64) : 1;
        int rows   = Lh / lsplit;
        idft_kernel<<<dim3(16,4,lsplit),256>>>(O, us+offs[i], ud+offs[i], Lh, m, inv_scale, rows);
        float* t; t=qc; qc=qn; qn=t;  t=kc; kc=kn; kn=t;
        L = Lh;
    }

    // v = FCA at L=1 = zeros; reconstruct upward
    float *vc=qc, *vn=qn;     // qc==bufA after 9 swaps? (9 odd -> qc==bufB); either buffer works
    zero_kernel<<<32,256>>>(vc, 16*1*512);
    int Lv = 1;
    for (int i=9;i>=0;i--){
        int total = 16*Lv*64;
        recon_kernel<<<(total+255)/256,256>>>(vc, us+offs[i], ud+offs[i],
                                              rc_e, rc_o, vn, Lv, total);
        float* t=vc; vc=vn; vn=t;
        Lv <<= 1;
    }

    // GEMM 3: out = vc @ out_w + out_b
    convW_kernel<<<gW,256>>>(out_w, Wthi, Wtlo);
    gemm_mma<<<gG,256,GEMM_SMEM>>>(vc, Wthi, Wtlo, out_b, outp);
}

// round 11
// speedup vs baseline: 2.2407x; 1.2760x over previous
#include <cuda_runtime.h>
#include <cuda_bf16.h>
#include <math.h>
#include <stdint.h>

// Problem constants
#define NB   16
#define NSEQ 1024
#define CK   512          // C*K

// -------- scratch (device globals; no allocation allowed) --------
__device__ float g_bufA[NB*NSEQ*CK];
__device__ float g_bufB[NB*NSEQ*CK];
__device__ float g_kA[NB*NSEQ*CK];
__device__ float g_kB[NB*NSEQ*CK];
__device__ float g_dq[NB*512*CK];
__device__ float g_dk[NB*512*CK];
__device__ float g_Us[NB*1023*CK];
__device__ float g_Ud[NB*1023*CK];
__device__ float g_S[NB*4*2*16*CK];   // spectra: (b, tensor{dq,dk,qn,kn}, re/im, mode, ck)
__device__ float g_O[NB*2*2*16*CK];   // post-attn spectra: (b, which{s,d}, re/im, mode, ck)
__device__ __nv_bfloat16 g_Wthi[CK*CK];
__device__ __nv_bfloat16 g_Wtlo[CK*CK];
__device__ __nv_bfloat16 g_W2hi[CK*CK];
__device__ __nv_bfloat16 g_W2lo[CK*CK];

__device__ __forceinline__ uint32_t smem_u32(const void* p){
    uint32_t a;
    asm("{ .reg .u64 t; cvta.to.shared.u64 t, %1; cvt.u32.u64 %0, t; }" : "=r"(a) : "l"(p));
    return a;
}

// W fp32 [K=512, N=512] row-major -> Wt hi/lo bf16 [N=512, K=512] (transposed)
__global__ __launch_bounds__(256) void convW_kernel(const float* __restrict__ W,
    __nv_bfloat16* __restrict__ hi, __nv_bfloat16* __restrict__ lo)
{
    __shared__ float t[32][33];
    int bx = blockIdx.x, by = blockIdx.y;
    int tx = threadIdx.x & 31, ty = threadIdx.x >> 5;
    for (int i = ty; i < 32; i += 8)
        t[i][tx] = W[(size_t)(bx*32 + i)*512 + by*32 + tx];
    __syncthreads();
    for (int i = ty; i < 32; i += 8){
        float v = t[tx][i];
        __nv_bfloat16 h = __float2bfloat16(v);
        size_t o = (size_t)(by*32 + i)*512 + bx*32 + tx;
        hi[o] = h;
        lo[o] = __float2bfloat16(v - __bfloat162float(h));
    }
}

// ================= tensor-core GEMM via mma.sync (bf16 split, fp32 accum) =================
// C[M,512] = A[M,512] @ W[512,512] + bias.  A read as fp32 and split in-kernel;
// W^T pre-split as (Bhi,Blo) [n][k] bf16.
// block tile 128x128, BK=32, 8 warps (2m x 4n), warp tile 64x32.
// smem per stage: 4 arrays x 128 rows x 40 halves (pad: 80B stride, conflict-free).
#define STAGE_BYTES 40960          // 4 * 128*40*2
#define ARR_BYTES   10240          // 128*40*2
#define GEMM_SMEM   (2*STAGE_BYTES)

__device__ __forceinline__ void mma16816(float* d, const uint32_t* a, uint32_t b0, uint32_t b1){
    asm volatile(
        "mma.sync.aligned.m16n8k16.row.col.f32.bf16.bf16.f32 "
        "{%0,%1,%2,%3}, {%4,%5,%6,%7}, {%8,%9}, {%0,%1,%2,%3};"
        : "+f"(d[0]), "+f"(d[1]), "+f"(d[2]), "+f"(d[3])
        : "r"(a[0]), "r"(a[1]), "r"(a[2]), "r"(a[3]), "r"(b0), "r"(b1));
}

__device__ __forceinline__ void ldsm4(uint32_t* r, uint32_t addr){
    asm volatile("ldmatrix.sync.aligned.m8n8.x4.shared.b16 {%0,%1,%2,%3}, [%4];"
        : "=r"(r[0]), "=r"(r[1]), "=r"(r[2]), "=r"(r[3]) : "r"(addr));
}

// B (Wthi/Wtlo) staging via cp.async (arrays 2,3 of the stage)
__device__ __forceinline__ void loadB_async(
    const __nv_bfloat16* __restrict__ Bhi, const __nv_bfloat16* __restrict__ Blo,
    int n0, int k0, uint32_t sstage, int tid)
{
    #pragma unroll
    for (int t = 4; t < 8; t++){
        const int arr = t >> 1;                 // 2 or 3
        const int row = (t & 1)*64 + (tid >> 2);
        const int seg = tid & 3;
        const __nv_bfloat16* g = ((arr == 2) ? Bhi : Blo) + (size_t)(n0 + row)*512 + k0 + seg*8;
        uint32_t d = sstage + arr*ARR_BYTES + row*80 + seg*16;
        asm volatile("cp.async.cg.shared.global [%0], [%1], 16;" :: "r"(d), "l"(g));
    }
}

// A fp32 chunk prefetch into regs: 2 tasks/thread, each 8 consecutive floats
__device__ __forceinline__ void prefetchA(const float* __restrict__ A,
    int m0, int k0, int tid, float4* pa)
{
    #pragma unroll
    for (int t = 0; t < 2; t++){
        int idx = tid + t*256;
        int row = idx >> 2, seg = idx & 3;
        const float* g = A + (size_t)(m0 + row)*512 + k0 + seg*8;
        pa[2*t]   = *(const float4*)g;
        pa[2*t+1] = *(const float4*)(g + 4);
    }
}

__device__ __forceinline__ uint32_t pack2(__nv_bfloat16 a, __nv_bfloat16 b){
    __nv_bfloat162 h; h.x = a; h.y = b;
    return *(uint32_t*)&h;
}

// convert prefetched A regs to hi/lo bf16 and store to stage (arrays 0,1)
__device__ __forceinline__ void stsA(uint32_t sstage, int tid, const float4* pa){
    #pragma unroll
    for (int t = 0; t < 2; t++){
        int idx = tid + t*256;
        int row = idx >> 2, seg = idx & 3;
        float4 v0 = pa[2*t], v1 = pa[2*t+1];
        __nv_bfloat16 h0 = __float2bfloat16(v0.x), h1 = __float2bfloat16(v0.y);
        __nv_bfloat16 h2 = __float2bfloat16(v0.z), h3 = __float2bfloat16(v0.w);
        __nv_bfloat16 h4 = __float2bfloat16(v1.x), h5 = __float2bfloat16(v1.y);
        __nv_bfloat16 h6 = __float2bfloat16(v1.z), h7 = __float2bfloat16(v1.w);
        uint4 hv;
        hv.x = pack2(h0, h1); hv.y = pack2(h2, h3);
        hv.z = pack2(h4, h5); hv.w = pack2(h6, h7);
        uint4 lv;
        lv.x = pack2(__float2bfloat16(v0.x - __bfloat162float(h0)),
                     __float2bfloat16(v0.y - __bfloat162float(h1)));
        lv.y = pack2(__float2bfloat16(v0.z - __bfloat162float(h2)),
                     __float2bfloat16(v0.w - __bfloat162float(h3)));
        lv.z = pack2(__float2bfloat16(v1.x - __bfloat162float(h4)),
                     __float2bfloat16(v1.y - __bfloat162float(h5)));
        lv.w = pack2(__float2bfloat16(v1.z - __bfloat162float(h6)),
                     __float2bfloat16(v1.w - __bfloat162float(h7)));
        uint32_t dhi = sstage + row*80 + seg*16;
        asm volatile("st.shared.v4.b32 [%0], {%1,%2,%3,%4};"
                     :: "r"(dhi), "r"(hv.x), "r"(hv.y), "r"(hv.z), "r"(hv.w) : "memory");
        asm volatile("st.shared.v4.b32 [%0], {%1,%2,%3,%4};"
                     :: "r"(dhi + ARR_BYTES), "r"(lv.x), "r"(lv.y), "r"(lv.z), "r"(lv.w) : "memory");
    }
}

__global__ __launch_bounds__(256,2) void gemm_mma(
    const float* __restrict__ A,
    const __nv_bfloat16* __restrict__ Bhi, const __nv_bfloat16* __restrict__ Blo,
    const float* __restrict__ bias, float* __restrict__ C)
{
    extern __shared__ char smem[];
    uint32_t sb = smem_u32(smem);
    const int tid  = threadIdx.x;
    const int lane = tid & 31, warp = tid >> 5;
    const int wm64 = (warp >> 2) * 64, wn32 = (warp & 3) * 32;
    const int grp  = lane >> 2,  q2   = (lane & 3) * 2;
    const int n0 = blockIdx.x * 128, m0 = blockIdx.y * 128;
    // ldmatrix per-lane address components
    const int lrow = (lane & 7) + ((lane >> 3) & 1) * 8;   // row within 16-row tile
    const int lcol = (lane >> 4) * 8;                       // col-half select

    float acc[4][4][4];
    #pragma unroll
    for (int i=0;i<4;i++)
        #pragma unroll
        for (int j=0;j<4;j++)
            #pragma unroll
            for (int r=0;r<4;r++) acc[i][j][r]=0.f;

    float4 pa[4];
    // prologue: stage chunks 0,1; prefetch chunk 2 into regs
    prefetchA(A, m0, 0, tid, pa);
    loadB_async(Bhi, Blo, n0, 0, sb, tid);
    asm volatile("cp.async.commit_group;" ::: "memory");
    stsA(sb, tid, pa);
    prefetchA(A, m0, 32, tid, pa);
    loadB_async(Bhi, Blo, n0, 32, sb + STAGE_BYTES, tid);
    asm volatile("cp.async.commit_group;" ::: "memory");
    stsA(sb + STAGE_BYTES, tid, pa);
    prefetchA(A, m0, 64, tid, pa);

    for (int c = 0; c < 16; c++){
        if (c < 15) asm volatile("cp.async.wait_group 1;" ::: "memory");
        else        asm volatile("cp.async.wait_group 0;" ::: "memory");
        __syncthreads();

        const uint32_t st = sb + (c & 1)*STAGE_BYTES;
        // per-warp ldmatrix bases (array offset added per pass)
        const uint32_t aBase = st + (wm64 + lrow)*80 + lcol*2;
        const uint32_t bBase = st + 2*ARR_BYTES + (wn32 + lrow)*80 + lcol*2;

        #pragma unroll
        for (int pass = 0; pass < 3; pass++){
            const uint32_t aOff = aBase + ((pass == 1) ? ARR_BYTES : 0);
            const uint32_t bOff = bBase + ((pass == 2) ? ARR_BYTES : 0);
            #pragma unroll
            for (int ks = 0; ks < 2; ks++){
                const uint32_t kb = ks*32;   // 16 halves = 32 bytes
                uint32_t aq[4][4], bq[2][4];
                #pragma unroll
                for (int mt = 0; mt < 4; mt++)
                    ldsm4(aq[mt], aOff + mt*16*80 + kb);
                ldsm4(bq[0], bOff + kb);
                ldsm4(bq[1], bOff + 16*80 + kb);
                #pragma unroll
                for (int mt = 0; mt < 4; mt++)
                    #pragma unroll
                    for (int nt = 0; nt < 4; nt++)
                        mma16816(acc[mt][nt], aq[mt],
                                 bq[nt>>1][nt&1], bq[nt>>1][2+(nt&1)]);
            }
        }
        __syncthreads();
        if (c + 2 < 16){
            uint32_t dst = sb + (c & 1)*STAGE_BYTES;
            loadB_async(Bhi, Blo, n0, (c+2)*32, dst, tid);
            asm volatile("cp.async.commit_group;" ::: "memory");
            stsA(dst, tid, pa);
            if (c + 3 < 16) prefetchA(A, m0, (c+3)*32, tid, pa);
        }
    }

    // epilogue: accum + bias -> C
    #pragma unroll
    for (int mt = 0; mt < 4; mt++){
        #pragma unroll
        for (int nt = 0; nt < 4; nt++){
            int r   = m0 + wm64 + mt*16 + grp;
            int col = n0 + wn32 + nt*8 + q2;
            float b0 = bias[col], b1 = bias[col+1];
            float2 v0 = make_float2(acc[mt][nt][0] + b0, acc[mt][nt][1] + b1);
            float2 v1 = make_float2(acc[mt][nt][2] + b0, acc[mt][nt][3] + b1);
            *(float2*)(C + (size_t)r*512 + col)     = v0;
            *(float2*)(C + (size_t)(r+8)*512 + col) = v1;
        }
    }
}

// ---------------- wavelet: x(b,2Lh,C,K) -> d,s (b,Lh,C,K) ----------------
__global__ __launch_bounds__(256) void wavelet_kernel(const float* __restrict__ x,
    float* __restrict__ d, float* __restrict__ s,
    const float* __restrict__ ecd, const float* __restrict__ ecs,
    int Lh, int total)
{
    __shared__ float wd[16][8], ws[16][8];
    int tid = threadIdx.x;
    if (tid < 128){ ((float*)wd)[tid] = ecd[tid]; ((float*)ws)[tid] = ecs[tid]; }
    __syncthreads();
    int idx = blockIdx.x*256 + tid;
    if (idx >= total) return;
    int c = idx & 63;
    int j = (idx >> 6) % Lh;
    int b = idx / (Lh << 6);
    const float* xe = x + (((size_t)b*(Lh<<1) + 2*j)*64 + c)*8;
    float xa[16];
    *(float4*)(xa)    = *(const float4*)(xe);
    *(float4*)(xa+4)  = *(const float4*)(xe+4);
    *(float4*)(xa+8)  = *(const float4*)(xe+512);
    *(float4*)(xa+12) = *(const float4*)(xe+516);
    float dv[8], sv[8];
    #pragma unroll
    for (int k=0;k<8;k++){ dv[k]=0.f; sv[k]=0.f; }
    #pragma unroll
    for (int t=0;t<16;t++){
        float xv = xa[t];
        #pragma unroll
        for (int k=0;k<8;k++){ dv[k] += xv*wd[t][k]; sv[k] += xv*ws[t][k]; }
    }
    float* dp = d + (size_t)idx*8;
    float* sp = s + (size_t)idx*8;
    *(float4*)(dp)   = make_float4(dv[0],dv[1],dv[2],dv[3]);
    *(float4*)(dp+4) = make_float4(dv[4],dv[5],dv[6],dv[7]);
    *(float4*)(sp)   = make_float4(sv[0],sv[1],sv[2],sv[3]);
    *(float4*)(sp+4) = make_float4(sv[4],sv[5],sv[6],sv[7]);
}

// ---------------- forward DFT (split-l, float2 twiddles) ----------------
// 256 threads = 128 cols x 2 l-halves; halves combined through smem.
__global__ __launch_bounds__(256) void dft_kernel(
    const float* __restrict__ t0, const float* __restrict__ t1,
    const float* __restrict__ t2, const float* __restrict__ t3,
    float* __restrict__ S, int Lh, int m)
{
    __shared__ float2 tw2[512];
    __shared__ float pr[16][128], pi[16][128];
    const int tid = threadIdx.x;
    const int b = blockIdx.x, tensor = blockIdx.y, ck0 = blockIdx.z * 128;
    for (int r = tid; r < Lh; r += 256){
        float sv, cv;
        sincosf(6.283185307179586f * ((float)r / (float)Lh), &sv, &cv);
        tw2[r] = make_float2(cv, sv);
    }
    __syncthreads();
    const float* X = (tensor==0) ? t0 : (tensor==1) ? t1 : (tensor==2) ? t2 : t3;
    const int col  = tid & 127;
    const int half = tid >> 7;
    const int Lh2  = Lh >> 1;
    const float* p = X + ((size_t)b*Lh + (size_t)half*Lh2)*512 + ck0 + col;
    float ar[16], ai[16];
    #pragma unroll
    for (int f=0; f<16; f++){ ar[f]=0.f; ai[f]=0.f; }
    for (int li=0; li<Lh2; li++){
        const int l = half*Lh2 + li;
        float xv = p[(size_t)li*512];
        int r = 0;
        #pragma unroll
        for (int f=0; f<16; f++){
            float2 t = tw2[r];
            ar[f] += xv * t.x;
            ai[f] += xv * t.y;
            r += l; if (r >= Lh) r -= Lh;
        }
    }
    if (half){
        #pragma unroll
        for (int f=0; f<16; f++){ pr[f][col]=ar[f]; pi[f][col]=ai[f]; }
    }
    __syncthreads();
    if (!half){
        float* out = S + (((size_t)b*4 + tensor)*2*16)*512 + ck0 + col;
        for (int f=0; f<m; f++){
            out[(size_t)f*512]        =  ar[f] + pr[f][col];     // real
            out[8192 + (size_t)f*512] = -(ai[f] + pi[f][col]);   // imag
        }
    }
}

// ---------------- mid: QK = ctanh(Sq^T Sk); O = QK Sk^T ----------------
__global__ __launch_bounds__(256) void mid_kernel(const float* __restrict__ S,
    float* __restrict__ O, int m)
{
    __shared__ float Sqr[64][16], Sqi[64][16], Skr[64][16], Ski[64][16];
    __shared__ float QKr[16][17], QKi[16][17];
    const int tid = threadIdx.x;
    const int b = blockIdx.x >> 3, h = blockIdx.x & 7;
    const int which = blockIdx.y;

    const float* base = S + (size_t)(b*4 + which*2)*2*16*512;
    for (int idx = tid; idx < 64*16; idx += 256){
        int e = idx >> 4, f = idx & 15;
        size_t o = (size_t)f*512 + e*8 + h;
        Sqr[e][f] = base[o];
        Sqi[e][f] = base[o + 8192];
        Skr[e][f] = base[o + 16384];
        Ski[e][f] = base[o + 24576];
    }
    __syncthreads();

    if (tid < m*m){
        int x = tid / m, y = tid - x*m;
        float sr=0.f, sim=0.f;
        #pragma unroll 8
        for (int e=0;e<64;e++){
            float qr=Sqr[e][x], qi=Sqi[e][x];
            float kr=Skr[e][y], ki=Ski[e][y];
            sr  += qr*kr - qi*ki;
            sim += qr*ki + qi*kr;
        }
        float txx = tanhf(sr);
        float tyy = tanf(sim);
        float tx2=txx*txx, ty2=tyy*tyy;
        float den = 1.0f + tx2*ty2;
        QKr[x][y] = txx*(1.0f+ty2)/den;
        QKi[x][y] = tyy*(1.0f-tx2)/den;
    }
    __syncthreads();

    float* ob = O + (size_t)(b*2 + which)*2*16*512;
    for (int t = tid; t < 64*m; t += 256){
        int x = t % m, e = t / m;
        float orr=0.f, oii=0.f;
        for (int y=0;y<m;y++){
            float ar=QKr[x][y], ai2=QKi[x][y];
            float br=Skr[e][y], bi=Ski[e][y];
            orr += ar*br - ai2*bi;
            oii += ar*bi + ai2*br;
        }
        size_t o = (size_t)x*512 + e*8 + h;
        ob[o]        = orr;
        ob[o + 8192] = oii;
    }
}

// ---------------- inverse DFT + fused add ----------------
__global__ __launch_bounds__(256) void idft_kernel(const float* __restrict__ O,
    float* __restrict__ Us, float* __restrict__ Ud,
    int Lh, int m, float scale, int rows)
{
    __shared__ float twc[512], tws[512];
    __shared__ float Osm[2][2][16][128];
    const int tid = threadIdx.x;
    const int b = blockIdx.x, ck0 = blockIdx.y * 128;
    for (int r = tid; r < Lh; r += 256){
        float sv, cv;
        sincosf(6.283185307179586f * ((float)r / (float)Lh), &sv, &cv);
        twc[r]=cv; tws[r]=sv;
    }
    for (int idx = tid; idx < 2*2*16*128; idx += 256){
        int w    = idx >> 12;
        int rem  = idx & 4095;
        int reim = rem >> 11;
        int f    = (rem >> 7) & 15;
        int col  = rem & 127;
        Osm[w][reim][f][col] =
            O[(size_t)((b*2 + w)*2 + reim)*8192 + (size_t)f*512 + ck0 + col];
    }
    __syncthreads();
    const int l0 = blockIdx.z * rows;
    for (int t = tid; t < rows*128; t += 256){
        int lr = t >> 7, col = t & 127;
        int l = l0 + lr;
        float as = Osm[0][0][0][col];
        float ad = Osm[1][0][0][col];
        int r = 0;
        for (int f=1; f<m; f++){
            r += l; if (r >= Lh) r -= Lh;
            float c = twc[r], s = tws[r];
            as += 2.0f*(Osm[0][0][f][col]*c - Osm[0][1][f][col]*s);
            ad += 2.0f*(Osm[1][0][f][col]*c - Osm[1][1][f][col]*s);
        }
        size_t oi = ((size_t)b*Lh + l)*512 + ck0 + col;
        float usv = as * scale;
        Us[oi] = usv;
        Ud[oi] = ad * scale + usv;
    }
}

// ---------------- reconstruction ----------------
__global__ __launch_bounds__(256) void recon_kernel(const float* __restrict__ v,
    const float* __restrict__ Us, const float* __restrict__ Ud,
    const float* __restrict__ rce, const float* __restrict__ rco,
    float* __restrict__ outv, int Lv, int total)
{
    __shared__ float we[16][8], wo[16][8];
    int tid = threadIdx.x;
    if (tid < 128){ ((float*)we)[tid] = rce[tid]; ((float*)wo)[tid] = rco[tid]; }
    __syncthreads();
    int idx = blockIdx.x*256 + tid;
    if (idx >= total) return;
    int c = idx & 63;
    int l = (idx >> 6) % Lv;
    int b = idx / (Lv << 6);
    const float* vp = v  + (size_t)idx*8;
    const float* up = Us + (size_t)idx*8;
    const float* dp = Ud + (size_t)idx*8;
    float w[16];
    #pragma unroll
    for (int t=0;t<8;t++) w[t]   = vp[t] + up[t];
    #pragma unroll
    for (int t=0;t<8;t++) w[8+t] = dp[t];
    float ev[8], ov[8];
    #pragma unroll
    for (int k=0;k<8;k++){ ev[k]=0.f; ov[k]=0.f; }
    #pragma unroll
    for (int t=0;t<16;t++){
        float xv = w[t];
        #pragma unroll
        for (int k=0;k<8;k++){ ev[k] += xv*we[t][k]; ov[k] += xv*wo[t][k]; }
    }
    float* op = outv + (((size_t)b*(Lv<<1) + 2*l)*64 + c)*8;
    *(float4*)(op)     = make_float4(ev[0],ev[1],ev[2],ev[3]);
    *(float4*)(op+4)   = make_float4(ev[4],ev[5],ev[6],ev[7]);
    *(float4*)(op+512) = make_float4(ov[0],ov[1],ov[2],ov[3]);
    *(float4*)(op+516) = make_float4(ov[4],ov[5],ov[6],ov[7]);
}

__global__ void zero_kernel(float* p, int n){
    int i = blockIdx.x*blockDim.x + threadIdx.x;
    if (i < n) p[i] = 0.f;
}

// ---------------- orchestration ----------------
extern "C" void kernel_launch(void* const* d_in, const int* in_sizes, int n_in,
                              void* d_out, int out_size)
{
    (void)in_sizes; (void)n_in; (void)out_size;
    const float* q     = (const float*)d_in[0];
    const float* k     = (const float*)d_in[1];
    // d_in[2] (v), d_in[7] (Lv_w), d_in[8] (Lv_b) provably unused by the math
    const float* Lq_w  = (const float*)d_in[3];
    const float* Lq_b  = (const float*)d_in[4];
    const float* Lk_w  = (const float*)d_in[5];
    const float* Lk_b  = (const float*)d_in[6];
    const float* out_w = (const float*)d_in[9];
    const float* out_b = (const float*)d_in[10];
    const float* ec_s  = (const float*)d_in[11];
    const float* ec_d  = (const float*)d_in[12];
    const float* rc_e  = (const float*)d_in[13];
    const float* rc_o  = (const float*)d_in[14];
    float* outp = (float*)d_out;

    float *bufA,*bufB,*kA,*kB,*dq,*dk,*us,*ud,*S,*O;
    __nv_bfloat16 *Wthi,*Wtlo,*W2hi,*W2lo;
    cudaGetSymbolAddress((void**)&bufA, g_bufA);
    cudaGetSymbolAddress((void**)&bufB, g_bufB);
    cudaGetSymbolAddress((void**)&kA,   g_kA);
    cudaGetSymbolAddress((void**)&kB,   g_kB);
    cudaGetSymbolAddress((void**)&dq,   g_dq);
    cudaGetSymbolAddress((void**)&dk,   g_dk);
    cudaGetSymbolAddress((void**)&us,   g_Us);
    cudaGetSymbolAddress((void**)&ud,   g_Ud);
    cudaGetSymbolAddress((void**)&S,    g_S);
    cudaGetSymbolAddress((void**)&O,    g_O);
    cudaGetSymbolAddress((void**)&Wthi, g_Wthi);
    cudaGetSymbolAddress((void**)&Wtlo, g_Wtlo);
    cudaGetSymbolAddress((void**)&W2hi, g_W2hi);
    cudaGetSymbolAddress((void**)&W2lo, g_W2lo);

    cudaFuncSetAttribute(gemm_mma, cudaFuncAttributeMaxDynamicSharedMemorySize, GEMM_SMEM);

    dim3 gW(16,16);
    dim3 gG(4,128);

    // precompute level offsets
    size_t offs[10]; size_t off=0;
    { int L = 1024;
      for (int i=0;i<10;i++){ int Lh = L >> 1; offs[i] = off; off += (size_t)16*Lh*512; L = Lh; } }

    // Launch order puts gemm_mma as this function's 4th launch: with the
    // harness's 2 pre-launches, ncu (-s 5 -c 1) profiles gemm_mma.
    zero_kernel<<<32,256>>>(us+offs[9], 16*1*512);           // level-9 Us = 0 (m=0)
    convW_kernel<<<gW,256>>>(Lq_w, Wthi, Wtlo);
    convW_kernel<<<gW,256>>>(Lk_w, W2hi, W2lo);
    gemm_mma<<<gG,256,GEMM_SMEM>>>(q, Wthi, Wtlo, Lq_b, bufA);
    gemm_mma<<<gG,256,GEMM_SMEM>>>(k, W2hi, W2lo, Lk_b, kA);
    zero_kernel<<<32,256>>>(ud+offs[9], 16*1*512);           // level-9 Ud = 0

    float *qc=bufA,*qn=bufB,*kc=kA,*kn=kB;
    int L = 1024;
    for (int i=0;i<9;i++){
        int Lh = L >> 1;
        int m  = (Lh>>1) < 16 ? (Lh>>1) : 16;
        int total = 16*Lh*64;
        int blocks = (total + 255)/256;
        wavelet_kernel<<<blocks,256>>>(qc, dq, qn, ec_d, ec_s, Lh, total);
        wavelet_kernel<<<blocks,256>>>(kc, dk, kn, ec_d, ec_s, Lh, total);
        dft_kernel<<<dim3(16,4,4),256>>>(dq, dk, qn, kn, S, Lh, m);
        mid_kernel<<<dim3(128,2),256>>>(S, O, m);
        float inv_scale = 1.0f/(4096.0f*(float)Lh);
        int lsplit = (Lh >= 64) ? (Lh/64) : 1;
        int rows   = Lh / lsplit;
        idft_kernel<<<dim3(16,4,lsplit),256>>>(O, us+offs[i], ud+offs[i], Lh, m, inv_scale, rows);
        float* t; t=qc; qc=qn; qn=t;  t=kc; kc=kn; kn=t;
        L = Lh;
    }

    // v = FCA at L=1 = zeros; reconstruct upward
    float *vc=qc, *vn=qn;
    zero_kernel<<<32,256>>>(vc, 16*1*512);
    int Lv = 1;
    for (int i=9;i>=0;i--){
        int total = 16*Lv*64;
        recon_kernel<<<(total+255)/256,256>>>(vc, us+offs[i], ud+offs[i],
                                              rc_e, rc_o, vn, Lv, total);
        float* t=vc; vc=vn; vn=t;
        Lv <<= 1;
    }

    // GEMM 3: out = vc @ out_w + out_b
    convW_kernel<<<gW,256>>>(out_w, Wthi, Wtlo);
    gemm_mma<<<gG,256,GEMM_SMEM>>>(vc, Wthi, Wtlo, out_b, outp);
}